// round 1
// baseline (speedup 1.0000x reference)
#include <cuda_runtime.h>
#include <math.h>

#define D 128
#define MAX_N   400000
#define MAX_E1  1000000
#define MAX_ENT 150000

// ---------------- device scratch (no allocs allowed) ----------------
__device__ float    g_nodesA[(size_t)MAX_N * D];
__device__ float    g_nodesB[(size_t)MAX_N * D];
__device__ float    g_hbuf  [(size_t)MAX_N * D];
__device__ float    g_dinv  [MAX_N];
__device__ int      g_deg   [MAX_N];
__device__ float    g_als   [MAX_ENT];
__device__ float    g_ald   [MAX_ENT];
__device__ float    g_aself [MAX_ENT];
__device__ unsigned g_m     [MAX_ENT];
__device__ float    g_z     [MAX_ENT];
__device__ int      g_cnt   [MAX_ENT];
__device__ float    g_lattr [MAX_ENT];
__device__ float    g_alpha [MAX_E1];
__device__ float    g_ce;

// ---------------- helpers ----------------
__device__ __forceinline__ unsigned long long pack2(float x){
    unsigned long long r; asm("mov.b64 %0, {%1, %1};" : "=l"(r) : "f"(x)); return r;
}
__device__ __forceinline__ void fma2(unsigned long long &d, unsigned long long a, unsigned long long b){
    asm("fma.rn.f32x2 %0, %1, %2, %0;" : "+l"(d) : "l"(a), "l"(b));
}
__device__ __forceinline__ float2 unpack2(unsigned long long v){
    float2 r; asm("mov.b64 {%0, %1}, %2;" : "=f"(r.x), "=f"(r.y) : "l"(v)); return r;
}
__device__ __forceinline__ unsigned f2ord(float f){
    unsigned u = __float_as_uint(f);
    return (u & 0x80000000u) ? ~u : (u | 0x80000000u);
}
__device__ __forceinline__ float ord2f(unsigned u){
    return __uint_as_float((u & 0x80000000u) ? (u ^ 0x80000000u) : ~u);
}
__device__ __forceinline__ float lrelu(float x){ return x > 0.f ? x : 0.2f * x; }

// ---------------- GEMM micro-kernel: 128x128 tile, 32-wide k slab ----------------
// As: [128 rows][36 stride] row-major (k local 0..31). Bs: [32 k][128 cols].
// 256 threads as 16x16; each thread owns 8 rows x 8 cols, acc packed as f32x2.
__device__ __forceinline__ void mm_ktile(const float* __restrict__ As, const float* __restrict__ Bs,
                                         unsigned long long (&acc)[8][4], int tx, int ty)
{
#pragma unroll
    for (int k4 = 0; k4 < 32; k4 += 4){
        float a_f[8][4];
#pragma unroll
        for (int i = 0; i < 8; ++i){
            float4 v = *(const float4*)(As + (ty*8 + i)*36 + k4);
            a_f[i][0]=v.x; a_f[i][1]=v.y; a_f[i][2]=v.z; a_f[i][3]=v.w;
        }
#pragma unroll
        for (int kk = 0; kk < 4; ++kk){
            const float* bp = Bs + (k4+kk)*D + tx*8;
            ulonglong2 b01 = *(const ulonglong2*)(bp);
            ulonglong2 b23 = *(const ulonglong2*)(bp + 4);
#pragma unroll
            for (int i = 0; i < 8; ++i){
                unsigned long long ad = pack2(a_f[i][kk]);
                fma2(acc[i][0], ad, b01.x);
                fma2(acc[i][1], ad, b01.y);
                fma2(acc[i][2], ad, b23.x);
                fma2(acc[i][3], ad, b23.y);
            }
        }
    }
}

__device__ __forceinline__ void mm_store(float* __restrict__ C, unsigned long long (&acc)[8][4],
                                         int m0, int M, int tx, int ty)
{
#pragma unroll
    for (int i = 0; i < 8; ++i){
        int row = m0 + ty*8 + i;
        if (row < M){
            float2 p0 = unpack2(acc[i][0]);
            float2 p1 = unpack2(acc[i][1]);
            float2 p2 = unpack2(acc[i][2]);
            float2 p3 = unpack2(acc[i][3]);
            float* cp = C + (size_t)row*D + tx*8;
            *(float4*)(cp)     = make_float4(p0.x, p0.y, p1.x, p1.y);
            *(float4*)(cp + 4) = make_float4(p2.x, p2.y, p3.x, p3.y);
        }
    }
}

// C[M,128] = A[M,128] @ B[128,128]
__global__ void __launch_bounds__(256, 2) k_gemm128(const float* __restrict__ A, const float* __restrict__ B,
                                                    float* __restrict__ C, int M)
{
    __shared__ float As[128*36];
    __shared__ float Bs[32*D];
    const int tid = threadIdx.x;
    const int tx = tid & 15, ty = tid >> 4;
    const int m0 = blockIdx.x * 128;
    unsigned long long acc[8][4];
#pragma unroll
    for (int i=0;i<8;i++)
#pragma unroll
        for (int j=0;j<4;j++) acc[i][j] = 0ull;

    for (int kt = 0; kt < 4; ++kt){
#pragma unroll
        for (int i = 0; i < 4; ++i){
            int f = tid + i*256;
            int r = f >> 3, p = (f & 7)*4;
            int row = m0 + r; if (row >= M) row = M - 1;
            *(float4*)(As + r*36 + p) = *(const float4*)(A + (size_t)row*D + kt*32 + p);
        }
#pragma unroll
        for (int i = 0; i < 4; ++i){
            int f = tid + i*256;
            int r = f >> 5, c = (f & 31)*4;
            *(float4*)(Bs + r*D + c) = *(const float4*)(B + (size_t)(kt*32 + r)*D + c);
        }
        __syncthreads();
        mm_ktile(As, Bs, acc, tx, ty);
        __syncthreads();
    }
    mm_store(C, acc, m0, M, tx, ty);
}

// C[t,:] = concat(att[a_t], val[v_t]) @ W  (K = 256, gathered A rows)
__global__ void __launch_bounds__(256, 2) k_valenc(const int* __restrict__ triples,
    const float* __restrict__ att, const float* __restrict__ val,
    const float* __restrict__ B, float* __restrict__ C, int T)
{
    __shared__ float As[128*36];
    __shared__ float Bs[32*D];
    __shared__ int idxA[128], idxV[128];
    const int tid = threadIdx.x;
    const int tx = tid & 15, ty = tid >> 4;
    const int m0 = blockIdx.x * 128;
    if (tid < 128){
        int t = m0 + tid; if (t >= T) t = T - 1;
        idxV[tid] = triples[3*t + 1];
        idxA[tid] = triples[3*t + 2];
    }
    unsigned long long acc[8][4];
#pragma unroll
    for (int i=0;i<8;i++)
#pragma unroll
        for (int j=0;j<4;j++) acc[i][j] = 0ull;
    __syncthreads();

    for (int kt = 0; kt < 8; ++kt){
#pragma unroll
        for (int i = 0; i < 4; ++i){
            int f = tid + i*256;
            int r = f >> 3, p = (f & 7)*4;
            const float* src = (kt < 4) ? (att + (size_t)idxA[r]*D + kt*32)
                                        : (val + (size_t)idxV[r]*D + (kt-4)*32);
            *(float4*)(As + r*36 + p) = *(const float4*)(src + p);
        }
#pragma unroll
        for (int i = 0; i < 4; ++i){
            int f = tid + i*256;
            int r = f >> 5, c = (f & 31)*4;
            *(float4*)(Bs + r*D + c) = *(const float4*)(B + (size_t)(kt*32 + r)*D + c);
        }
        __syncthreads();
        mm_ktile(As, Bs, acc, tx, ty);
        __syncthreads();
    }
    mm_store(C, acc, m0, T, tx, ty);
}

// ---------------- elementwise / edge kernels ----------------
__global__ void k_copy4(const float4* __restrict__ s, float4* __restrict__ d, int n){
    int i = blockIdx.x*blockDim.x + threadIdx.x;
    if (i < n) d[i] = s[i];
}
__global__ void k_seti(int* p, int v, int n){
    int i = blockIdx.x*blockDim.x + threadIdx.x; if (i < n) p[i] = v;
}
__global__ void k_setf(float* p, float v, int n){
    int i = blockIdx.x*blockDim.x + threadIdx.x; if (i < n) p[i] = v;
}
__global__ void k_deg_acc(const int* __restrict__ ed, int* deg, int E){
    int i = blockIdx.x*blockDim.x + threadIdx.x;
    if (i < E) atomicAdd(deg + ed[2*i+1], 1);
}
__global__ void k_dinv(const int* __restrict__ deg, float* __restrict__ dinv, int n){
    int i = blockIdx.x*blockDim.x + threadIdx.x;
    if (i < n) dinv[i] = rsqrtf((float)deg[i]);
}
// out[j] = b + dinv[j]^2 * h[j]   (self loop + bias init)
__global__ void k_self_gcn(const float4* __restrict__ h, const float* __restrict__ dinv,
                           const float* __restrict__ b, float4* __restrict__ out, int M){
    int i = blockIdx.x*blockDim.x + threadIdx.x;
    if (i < M*32){
        int j = i >> 5, c = (i & 31)*4;
        float s = dinv[j]; s *= s;
        float4 hv = h[i];
        float4 bv = *(const float4*)(b + c);
        out[i] = make_float4(bv.x + s*hv.x, bv.y + s*hv.y, bv.z + s*hv.z, bv.w + s*hv.w);
    }
}
// warp per edge: out[d] += dinv[s]*dinv[d] * h[s]
__global__ void k_gcn_edge(const int* __restrict__ ed, const float* __restrict__ h,
                           const float* __restrict__ dinv, float* __restrict__ out, int E, int maxd){
    int g = blockIdx.x*blockDim.x + threadIdx.x;
    int lane = g & 31, e = g >> 5;
    if (e >= E) return;
    int s = ed[2*e], d = ed[2*e+1];
    if (d >= maxd) return;
    float nrm = dinv[s]*dinv[d];
    float4 hv = *(const float4*)(h + (size_t)s*D + lane*4);
    float* o = out + (size_t)d*D + lane*4;
    atomicAdd(o,   nrm*hv.x); atomicAdd(o+1, nrm*hv.y);
    atomicAdd(o+2, nrm*hv.z); atomicAdd(o+3, nrm*hv.w);
}
__global__ void k_cnt(const int* __restrict__ ed, const float* __restrict__ lab,
                      int* cnt, float* ls, int E){
    int i = blockIdx.x*blockDim.x + threadIdx.x;
    if (i < E){ int d = ed[2*i+1]; atomicAdd(cnt + d, 1); atomicAdd(ls + d, lab[i]); }
}
__global__ void k_lattr(const int* __restrict__ cnt, float* __restrict__ ls, int n){
    int i = blockIdx.x*blockDim.x + threadIdx.x;
    if (i < n) ls[i] = ls[i] / fmaxf((float)cnt[i], 1.f);
}
__global__ void k_ce(const float* __restrict__ We, const float* __restrict__ ae){
    __shared__ float s[D];
    int t = threadIdx.x;
    s[t] = We[t]*ae[t];
    __syncthreads();
    if (t == 0){ float a = 0.f; for (int i = 0; i < D; i++) a += s[i]; g_ce = a; }
}
// warp per row: als = h.asrc, ald = h.adst
__global__ void k_als(const float* __restrict__ h, const float* __restrict__ asrc,
                      const float* __restrict__ adst, float* als, float* ald, int M){
    int g = blockIdx.x*blockDim.x + threadIdx.x;
    int lane = g & 31, row = g >> 5;
    if (row >= M) return;
    float4 hv = *(const float4*)(h + (size_t)row*D + lane*4);
    float4 sv = *(const float4*)(asrc + lane*4);
    float4 dv = *(const float4*)(adst + lane*4);
    float x = hv.x*sv.x + hv.y*sv.y + hv.z*sv.z + hv.w*sv.w;
    float y = hv.x*dv.x + hv.y*dv.y + hv.z*dv.z + hv.w*dv.w;
#pragma unroll
    for (int o = 16; o; o >>= 1){
        x += __shfl_xor_sync(0xffffffffu, x, o);
        y += __shfl_xor_sync(0xffffffffu, y, o);
    }
    if (lane == 0){ als[row] = x; ald[row] = y; }
}
__global__ void k_minit(const float* __restrict__ als, const float* __restrict__ ald,
                        const float* __restrict__ la, float* aself, unsigned* m, int n){
    int i = blockIdx.x*blockDim.x + threadIdx.x;
    if (i < n){
        float a = lrelu(als[i] + ald[i] + la[i]*g_ce);
        aself[i] = a; m[i] = f2ord(a);
    }
}
__global__ void k_alpha(const int* __restrict__ ed, const float* __restrict__ lab,
                        const float* __restrict__ als, const float* __restrict__ ald,
                        float* __restrict__ alpha, unsigned* __restrict__ m, int E){
    int i = blockIdx.x*blockDim.x + threadIdx.x;
    if (i < E){
        int s = ed[2*i], d = ed[2*i+1];
        float a = lrelu(als[s] + ald[d] + lab[i]*g_ce);
        alpha[i] = a;
        atomicMax(m + d, f2ord(a));
    }
}
__global__ void k_zinit(const float* __restrict__ aself, const unsigned* __restrict__ m,
                        float* __restrict__ z, int n){
    int i = blockIdx.x*blockDim.x + threadIdx.x;
    if (i < n) z[i] = expf(aself[i] - ord2f(m[i]));
}
__global__ void k_zacc(const int* __restrict__ ed, const float* __restrict__ alpha,
                       const unsigned* __restrict__ m, float* __restrict__ z, int E){
    int i = blockIdx.x*blockDim.x + threadIdx.x;
    if (i < E){ int d = ed[2*i+1]; atomicAdd(z + d, expf(alpha[i] - ord2f(m[d]))); }
}
// out = ent_feats + gat1_b + gat2_b
__global__ void k_outinit(const float4* __restrict__ ent, const float* __restrict__ b1,
                          const float* __restrict__ b2, float4* __restrict__ out, int M){
    int i = blockIdx.x*blockDim.x + threadIdx.x;
    if (i < M*32){
        int c = (i & 31)*4;
        float4 e = ent[i];
        float4 v1 = *(const float4*)(b1 + c);
        float4 v2 = *(const float4*)(b2 + c);
        out[i] = make_float4(e.x+v1.x+v2.x, e.y+v1.y+v2.y, e.z+v1.z+v2.z, e.w+v1.w+v2.w);
    }
}
// out[j] += wself * h[j]
__global__ void k_self_gat(const float4* __restrict__ h, const float* __restrict__ aself,
                           const unsigned* __restrict__ m, const float* __restrict__ z,
                           float4* __restrict__ out, int M){
    int i = blockIdx.x*blockDim.x + threadIdx.x;
    if (i < M*32){
        int j = i >> 5;
        float w = expf(aself[j] - ord2f(m[j])) / (z[j] + 1e-16f);
        float4 hv = h[i]; float4 o = out[i];
        out[i] = make_float4(o.x + w*hv.x, o.y + w*hv.y, o.z + w*hv.z, o.w + w*hv.w);
    }
}
// warp per edge: out[d] += w_e * h[s]
__global__ void k_gat_edge(const int* __restrict__ ed, const float* __restrict__ alpha,
                           const unsigned* __restrict__ m, const float* __restrict__ z,
                           const float* __restrict__ h, float* __restrict__ out, int E){
    int g = blockIdx.x*blockDim.x + threadIdx.x;
    int lane = g & 31, e = g >> 5;
    if (e >= E) return;
    int s = ed[2*e], d = ed[2*e+1];
    float w = expf(alpha[e] - ord2f(m[d])) / (z[d] + 1e-16f);
    float4 hv = *(const float4*)(h + (size_t)s*D + lane*4);
    float* o = out + (size_t)d*D + lane*4;
    atomicAdd(o,   w*hv.x); atomicAdd(o+1, w*hv.y);
    atomicAdd(o+2, w*hv.z); atomicAdd(o+3, w*hv.w);
}

// ---------------- launcher ----------------
extern "C" void kernel_launch(void* const* d_in, const int* in_sizes, int n_in,
                              void* d_out, int out_size)
{
    const int*   triples  = (const int*)  d_in[0];
    const int*   ent_ed   = (const int*)  d_in[1];
    const float* ent_lab  = (const float*)d_in[2];
    const int*   val_ed   = (const int*)  d_in[3];
    const float* att      = (const float*)d_in[5];
    const float* valf     = (const float*)d_in[6];
    const float* entf     = (const float*)d_in[7];
    const float* Wp       = (const float*)d_in[8];
    const float* g1W      = (const float*)d_in[9];
    const float* g1b      = (const float*)d_in[10];
    const float* g2W      = (const float*)d_in[11];
    const float* g2b      = (const float*)d_in[12];
    const float* Wl[2]  = {(const float*)d_in[13], (const float*)d_in[19]};
    const float* asr[2] = {(const float*)d_in[14], (const float*)d_in[20]};
    const float* ads[2] = {(const float*)d_in[15], (const float*)d_in[21]};
    const float* Wev[2] = {(const float*)d_in[16], (const float*)d_in[22]};
    const float* aev[2] = {(const float*)d_in[17], (const float*)d_in[23]};
    const float* gb1      = (const float*)d_in[18];
    const float* gb2      = (const float*)d_in[24];

    const int T   = in_sizes[0] / 3;
    const int E1  = in_sizes[1] / 2;
    const int E2  = in_sizes[3] / 2;
    const int NE  = in_sizes[7] / D;   // num_ent
    const int N   = NE + T;
    float* out = (float*)d_out;

    float *nodesA, *nodesB, *hbuf, *dinv, *als, *ald, *aself, *z, *lattr, *alpha;
    int *deg, *cnt; unsigned *mbuf;
    cudaGetSymbolAddress((void**)&nodesA, g_nodesA);
    cudaGetSymbolAddress((void**)&nodesB, g_nodesB);
    cudaGetSymbolAddress((void**)&hbuf,   g_hbuf);
    cudaGetSymbolAddress((void**)&dinv,   g_dinv);
    cudaGetSymbolAddress((void**)&deg,    g_deg);
    cudaGetSymbolAddress((void**)&als,    g_als);
    cudaGetSymbolAddress((void**)&ald,    g_ald);
    cudaGetSymbolAddress((void**)&aself,  g_aself);
    cudaGetSymbolAddress((void**)&mbuf,   g_m);
    cudaGetSymbolAddress((void**)&z,      g_z);
    cudaGetSymbolAddress((void**)&cnt,    g_cnt);
    cudaGetSymbolAddress((void**)&lattr,  g_lattr);
    cudaGetSymbolAddress((void**)&alpha,  g_alpha);

    const int TB = 256;
    #define GRID1(n) (((n) + TB - 1) / TB)

    // ---- build node features ----
    k_copy4 <<<GRID1(NE*32), TB>>>((const float4*)entf, (float4*)nodesA, NE*32);
    k_valenc<<<(T + 127)/128, TB>>>(triples, att, valf, Wp, nodesA + (size_t)NE*D, T);

    // ---- degree / norm for GCN ----
    k_seti  <<<GRID1(N), TB>>>(deg, 1, N);
    k_deg_acc<<<GRID1(E2), TB>>>(val_ed, deg, E2);
    k_dinv  <<<GRID1(N), TB>>>(deg, dinv, N);

    // ---- GCN layer 1 (full N output needed) ----
    k_gemm128 <<<(N + 127)/128, TB>>>(nodesA, g1W, hbuf, N);
    k_self_gcn<<<GRID1(N*32), TB>>>((const float4*)hbuf, dinv, g1b, (float4*)nodesB, N);
    k_gcn_edge<<<(E2 + 7)/8, TB>>>(val_ed, hbuf, dinv, nodesB, E2, N);

    // ---- GCN layer 2 (only entity rows consumed downstream) ----
    k_gemm128 <<<(N + 127)/128, TB>>>(nodesB, g2W, hbuf, N);
    k_self_gcn<<<GRID1(NE*32), TB>>>((const float4*)hbuf, dinv, g2b, (float4*)nodesA, NE);
    k_gcn_edge<<<(E2 + 7)/8, TB>>>(val_ed, hbuf, dinv, nodesA, E2, NE);

    // ---- GAT shared prep ----
    k_seti <<<GRID1(NE), TB>>>(cnt, 0, NE);
    k_setf <<<GRID1(NE), TB>>>(lattr, 0.f, NE);
    k_cnt  <<<GRID1(E1), TB>>>(ent_ed, ent_lab, cnt, lattr, E1);
    k_lattr<<<GRID1(NE), TB>>>(cnt, lattr, NE);
    k_outinit<<<GRID1(NE*32), TB>>>((const float4*)entf, gb1, gb2, (float4*)out, NE);

    // ---- two GAT layers ----
    for (int g = 0; g < 2; ++g){
        k_gemm128<<<(NE + 127)/128, TB>>>(nodesA, Wl[g], hbuf, NE);
        k_ce     <<<1, 128>>>(Wev[g], aev[g]);
        k_als    <<<(NE + 7)/8, TB>>>(hbuf, asr[g], ads[g], als, ald, NE);
        k_minit  <<<GRID1(NE), TB>>>(als, ald, lattr, aself, mbuf, NE);
        k_alpha  <<<GRID1(E1), TB>>>(ent_ed, ent_lab, als, ald, alpha, mbuf, E1);
        k_zinit  <<<GRID1(NE), TB>>>(aself, mbuf, z, NE);
        k_zacc   <<<GRID1(E1), TB>>>(ent_ed, alpha, mbuf, z, E1);
        k_self_gat<<<GRID1(NE*32), TB>>>((const float4*)hbuf, aself, mbuf, z, (float4*)out, NE);
        k_gat_edge<<<(E1 + 7)/8, TB>>>(ent_ed, alpha, mbuf, z, hbuf, out, E1);
    }
    #undef GRID1
}

// round 2
// speedup vs baseline: 1.2803x; 1.2803x over previous
#include <cuda_runtime.h>
#include <math.h>

#define D 128
#define MAX_N   400000
#define MAX_E1  1000000
#define MAX_ENT 150000

// ---------------- device scratch (no allocs allowed) ----------------
__device__ float    g_nodesA[(size_t)MAX_N * D];
__device__ float    g_nodesB[(size_t)MAX_N * D];
__device__ float    g_hbuf  [(size_t)MAX_N * D];   // GCN h; GAT: h1=[0,NE), h2=[NE,2NE)
__device__ float    g_dinv  [MAX_N];
__device__ int      g_deg   [MAX_N];
__device__ float2   g_als2  [MAX_ENT];
__device__ float2   g_ald2  [MAX_ENT];
__device__ float2   g_aself2[MAX_ENT];
__device__ uint2    g_m2    [MAX_ENT];
__device__ float2   g_z2    [MAX_ENT];
__device__ int      g_cnt   [MAX_ENT];
__device__ float    g_lattr [MAX_ENT];
__device__ float2   g_alpha2[MAX_E1];
__device__ float    g_ce2[2];

// ---------------- helpers ----------------
__device__ __forceinline__ unsigned long long pack2(float x){
    unsigned long long r; asm("mov.b64 %0, {%1, %1};" : "=l"(r) : "f"(x)); return r;
}
__device__ __forceinline__ void fma2(unsigned long long &d, unsigned long long a, unsigned long long b){
    asm("fma.rn.f32x2 %0, %1, %2, %0;" : "+l"(d) : "l"(a), "l"(b));
}
__device__ __forceinline__ float2 unpack2(unsigned long long v){
    float2 r; asm("mov.b64 {%0, %1}, %2;" : "=f"(r.x), "=f"(r.y) : "l"(v)); return r;
}
__device__ __forceinline__ unsigned f2ord(float f){
    unsigned u = __float_as_uint(f);
    return (u & 0x80000000u) ? ~u : (u | 0x80000000u);
}
__device__ __forceinline__ float ord2f(unsigned u){
    return __uint_as_float((u & 0x80000000u) ? (u ^ 0x80000000u) : ~u);
}
__device__ __forceinline__ float lrelu(float x){ return x > 0.f ? x : 0.2f * x; }
// vectorized global reduction: one RED.128 instead of 4 scalar atomics
__device__ __forceinline__ void red4(float* p, float4 v){
    asm volatile("red.global.add.v4.f32 [%0], {%1,%2,%3,%4};"
        :: "l"(p), "f"(v.x), "f"(v.y), "f"(v.z), "f"(v.w) : "memory");
}

// ---------------- GEMM micro-kernel: 128x128 tile, 32-wide k slab ----------------
__device__ __forceinline__ void mm_ktile(const float* __restrict__ As, const float* __restrict__ Bs,
                                         unsigned long long (&acc)[8][4], int tx, int ty)
{
#pragma unroll
    for (int k4 = 0; k4 < 32; k4 += 4){
        float a_f[8][4];
#pragma unroll
        for (int i = 0; i < 8; ++i){
            float4 v = *(const float4*)(As + (ty*8 + i)*36 + k4);
            a_f[i][0]=v.x; a_f[i][1]=v.y; a_f[i][2]=v.z; a_f[i][3]=v.w;
        }
#pragma unroll
        for (int kk = 0; kk < 4; ++kk){
            const float* bp = Bs + (k4+kk)*D + tx*8;
            ulonglong2 b01 = *(const ulonglong2*)(bp);
            ulonglong2 b23 = *(const ulonglong2*)(bp + 4);
#pragma unroll
            for (int i = 0; i < 8; ++i){
                unsigned long long ad = pack2(a_f[i][kk]);
                fma2(acc[i][0], ad, b01.x);
                fma2(acc[i][1], ad, b01.y);
                fma2(acc[i][2], ad, b23.x);
                fma2(acc[i][3], ad, b23.y);
            }
        }
    }
}

__device__ __forceinline__ void mm_store(float* __restrict__ C, unsigned long long (&acc)[8][4],
                                         int m0, int M, int tx, int ty)
{
#pragma unroll
    for (int i = 0; i < 8; ++i){
        int row = m0 + ty*8 + i;
        if (row < M){
            float2 p0 = unpack2(acc[i][0]);
            float2 p1 = unpack2(acc[i][1]);
            float2 p2 = unpack2(acc[i][2]);
            float2 p3 = unpack2(acc[i][3]);
            float* cp = C + (size_t)row*D + tx*8;
            *(float4*)(cp)     = make_float4(p0.x, p0.y, p1.x, p1.y);
            *(float4*)(cp + 4) = make_float4(p2.x, p2.y, p3.x, p3.y);
        }
    }
}

__global__ void __launch_bounds__(256, 2) k_gemm128(const float* __restrict__ A, const float* __restrict__ B,
                                                    float* __restrict__ C, int M)
{
    __shared__ float As[128*36];
    __shared__ float Bs[32*D];
    const int tid = threadIdx.x;
    const int tx = tid & 15, ty = tid >> 4;
    const int m0 = blockIdx.x * 128;
    unsigned long long acc[8][4];
#pragma unroll
    for (int i=0;i<8;i++)
#pragma unroll
        for (int j=0;j<4;j++) acc[i][j] = 0ull;

    for (int kt = 0; kt < 4; ++kt){
#pragma unroll
        for (int i = 0; i < 4; ++i){
            int f = tid + i*256;
            int r = f >> 3, p = (f & 7)*4;
            int row = m0 + r; if (row >= M) row = M - 1;
            *(float4*)(As + r*36 + p) = *(const float4*)(A + (size_t)row*D + kt*32 + p);
        }
#pragma unroll
        for (int i = 0; i < 4; ++i){
            int f = tid + i*256;
            int r = f >> 5, c = (f & 31)*4;
            *(float4*)(Bs + r*D + c) = *(const float4*)(B + (size_t)(kt*32 + r)*D + c);
        }
        __syncthreads();
        mm_ktile(As, Bs, acc, tx, ty);
        __syncthreads();
    }
    mm_store(C, acc, m0, M, tx, ty);
}

// C[t,:] = concat(att[a_t], val[v_t]) @ W  (K = 256, gathered A rows)
__global__ void __launch_bounds__(256, 2) k_valenc(const int* __restrict__ triples,
    const float* __restrict__ att, const float* __restrict__ val,
    const float* __restrict__ B, float* __restrict__ C, int T)
{
    __shared__ float As[128*36];
    __shared__ float Bs[32*D];
    __shared__ int idxA[128], idxV[128];
    const int tid = threadIdx.x;
    const int tx = tid & 15, ty = tid >> 4;
    const int m0 = blockIdx.x * 128;
    if (tid < 128){
        int t = m0 + tid; if (t >= T) t = T - 1;
        idxV[tid] = triples[3*t + 1];
        idxA[tid] = triples[3*t + 2];
    }
    unsigned long long acc[8][4];
#pragma unroll
    for (int i=0;i<8;i++)
#pragma unroll
        for (int j=0;j<4;j++) acc[i][j] = 0ull;
    __syncthreads();

    for (int kt = 0; kt < 8; ++kt){
#pragma unroll
        for (int i = 0; i < 4; ++i){
            int f = tid + i*256;
            int r = f >> 3, p = (f & 7)*4;
            const float* src = (kt < 4) ? (att + (size_t)idxA[r]*D + kt*32)
                                        : (val + (size_t)idxV[r]*D + (kt-4)*32);
            *(float4*)(As + r*36 + p) = *(const float4*)(src + p);
        }
#pragma unroll
        for (int i = 0; i < 4; ++i){
            int f = tid + i*256;
            int r = f >> 5, c = (f & 31)*4;
            *(float4*)(Bs + r*D + c) = *(const float4*)(B + (size_t)(kt*32 + r)*D + c);
        }
        __syncthreads();
        mm_ktile(As, Bs, acc, tx, ty);
        __syncthreads();
    }
    mm_store(C, acc, m0, T, tx, ty);
}

// ---------------- elementwise / edge kernels ----------------
__global__ void k_copy4(const float4* __restrict__ s, float4* __restrict__ d, int n){
    int i = blockIdx.x*blockDim.x + threadIdx.x;
    if (i < n) d[i] = s[i];
}
__global__ void k_seti(int* p, int v, int n){
    int i = blockIdx.x*blockDim.x + threadIdx.x; if (i < n) p[i] = v;
}
__global__ void k_setf(float* p, float v, int n){
    int i = blockIdx.x*blockDim.x + threadIdx.x; if (i < n) p[i] = v;
}
__global__ void k_deg_acc(const int2* __restrict__ ed, int* deg, int E){
    int i = blockIdx.x*blockDim.x + threadIdx.x;
    if (i < E) atomicAdd(deg + ed[i].y, 1);
}
__global__ void k_dinv(const int* __restrict__ deg, float* __restrict__ dinv, int n){
    int i = blockIdx.x*blockDim.x + threadIdx.x;
    if (i < n) dinv[i] = rsqrtf((float)deg[i]);
}
// out[j] = b + dinv[j]^2 * h[j]   (self loop + bias init)
__global__ void k_self_gcn(const float4* __restrict__ h, const float* __restrict__ dinv,
                           const float* __restrict__ b, float4* __restrict__ out, int M){
    int i = blockIdx.x*blockDim.x + threadIdx.x;
    if (i < M*32){
        int j = i >> 5, c = (i & 31)*4;
        float s = dinv[j]; s *= s;
        float4 hv = h[i];
        float4 bv = *(const float4*)(b + c);
        out[i] = make_float4(bv.x + s*hv.x, bv.y + s*hv.y, bv.z + s*hv.z, bv.w + s*hv.w);
    }
}
// warp per edge: out[d] += dinv[s]*dinv[d] * h[s]
__global__ void k_gcn_edge(const int2* __restrict__ ed, const float* __restrict__ h,
                           const float* __restrict__ dinv, float* __restrict__ out, int E, int maxd){
    int g = blockIdx.x*blockDim.x + threadIdx.x;
    int lane = g & 31, e = g >> 5;
    if (e >= E) return;
    int2 sd = ed[e];
    if (sd.y >= maxd) return;
    float nrm = dinv[sd.x]*dinv[sd.y];
    float4 hv = *(const float4*)(h + (size_t)sd.x*D + lane*4);
    red4(out + (size_t)sd.y*D + lane*4,
         make_float4(nrm*hv.x, nrm*hv.y, nrm*hv.z, nrm*hv.w));
}
__global__ void k_cnt(const int2* __restrict__ ed, const float* __restrict__ lab,
                      int* cnt, float* ls, int E){
    int i = blockIdx.x*blockDim.x + threadIdx.x;
    if (i < E){ int d = ed[i].y; atomicAdd(cnt + d, 1); atomicAdd(ls + d, lab[i]); }
}
__global__ void k_lattr(const int* __restrict__ cnt, float* __restrict__ ls, int n){
    int i = blockIdx.x*blockDim.x + threadIdx.x;
    if (i < n) ls[i] = ls[i] / fmaxf((float)cnt[i], 1.f);
}
// ce[g] = sum We_g[i]*ae_g[i]
__global__ void k_ce2(const float* __restrict__ We1, const float* __restrict__ ae1,
                      const float* __restrict__ We2, const float* __restrict__ ae2){
    int t = threadIdx.x;             // 64 threads, 2 warps
    int lane = t & 31, w = t >> 5;
    const float* We = w ? We2 : We1;
    const float* ae = w ? ae2 : ae1;
    float s = 0.f;
    for (int i = lane; i < D; i += 32) s += We[i]*ae[i];
#pragma unroll
    for (int o = 16; o; o >>= 1) s += __shfl_xor_sync(0xffffffffu, s, o);
    if (lane == 0) g_ce2[w] = s;
}
// warp per row: als/ald for both layers + self alpha + m init (fused)
__global__ void k_att_fused(const float* __restrict__ h1, const float* __restrict__ h2,
    const float* __restrict__ as1, const float* __restrict__ ad1,
    const float* __restrict__ as2, const float* __restrict__ ad2,
    const float* __restrict__ lattr, int M)
{
    int g = blockIdx.x*blockDim.x + threadIdx.x;
    int lane = g & 31, row = g >> 5;
    if (row >= M) return;
    float4 h1v = *(const float4*)(h1 + (size_t)row*D + lane*4);
    float4 h2v = *(const float4*)(h2 + (size_t)row*D + lane*4);
    float4 s1 = *(const float4*)(as1 + lane*4);
    float4 d1 = *(const float4*)(ad1 + lane*4);
    float4 s2 = *(const float4*)(as2 + lane*4);
    float4 d2 = *(const float4*)(ad2 + lane*4);
    float x1 = h1v.x*s1.x + h1v.y*s1.y + h1v.z*s1.z + h1v.w*s1.w;
    float y1 = h1v.x*d1.x + h1v.y*d1.y + h1v.z*d1.z + h1v.w*d1.w;
    float x2 = h2v.x*s2.x + h2v.y*s2.y + h2v.z*s2.z + h2v.w*s2.w;
    float y2 = h2v.x*d2.x + h2v.y*d2.y + h2v.z*d2.z + h2v.w*d2.w;
#pragma unroll
    for (int o = 16; o; o >>= 1){
        x1 += __shfl_xor_sync(0xffffffffu, x1, o);
        y1 += __shfl_xor_sync(0xffffffffu, y1, o);
        x2 += __shfl_xor_sync(0xffffffffu, x2, o);
        y2 += __shfl_xor_sync(0xffffffffu, y2, o);
    }
    if (lane == 0){
        float la = lattr[row];
        g_als2[row] = make_float2(x1, x2);
        g_ald2[row] = make_float2(y1, y2);
        float a1 = lrelu(x1 + y1 + la*g_ce2[0]);
        float a2 = lrelu(x2 + y2 + la*g_ce2[1]);
        g_aself2[row] = make_float2(a1, a2);
        g_m2[row] = make_uint2(f2ord(a1), f2ord(a2));
    }
}
// per edge: alphas for both layers + running segment max
__global__ void k_alpha2(const int2* __restrict__ ed, const float* __restrict__ lab, int E){
    int i = blockIdx.x*blockDim.x + threadIdx.x;
    if (i >= E) return;
    int2 sd = ed[i];
    float2 als = g_als2[sd.x];
    float2 ald = g_ald2[sd.y];
    float la = lab[i];
    float a1 = lrelu(als.x + ald.x + la*g_ce2[0]);
    float a2 = lrelu(als.y + ald.y + la*g_ce2[1]);
    g_alpha2[i] = make_float2(a1, a2);
    atomicMax(&g_m2[sd.y].x, f2ord(a1));
    atomicMax(&g_m2[sd.y].y, f2ord(a2));
}
__global__ void k_z2init(int n){
    int i = blockIdx.x*blockDim.x + threadIdx.x;
    if (i < n){
        float2 a = g_aself2[i]; uint2 m = g_m2[i];
        g_z2[i] = make_float2(__expf(a.x - ord2f(m.x)), __expf(a.y - ord2f(m.y)));
    }
}
__global__ void k_z2acc(const int2* __restrict__ ed, int E){
    int i = blockIdx.x*blockDim.x + threadIdx.x;
    if (i >= E) return;
    int d = ed[i].y;
    float2 a = g_alpha2[i]; uint2 m = g_m2[d];
    atomicAdd(&g_z2[d].x, __expf(a.x - ord2f(m.x)));
    atomicAdd(&g_z2[d].y, __expf(a.y - ord2f(m.y)));
}
// out = ent + b1 + b2 + w1self*h1 + w2self*h2
__global__ void k_self2(const float4* __restrict__ ent, const float* __restrict__ b1,
                        const float* __restrict__ b2, const float4* __restrict__ h1,
                        const float4* __restrict__ h2, float4* __restrict__ out, int M){
    int i = blockIdx.x*blockDim.x + threadIdx.x;
    if (i < M*32){
        int j = i >> 5, c = (i & 31)*4;
        float2 a = g_aself2[j]; uint2 m = g_m2[j]; float2 z = g_z2[j];
        float w1 = __expf(a.x - ord2f(m.x)) / (z.x + 1e-16f);
        float w2 = __expf(a.y - ord2f(m.y)) / (z.y + 1e-16f);
        float4 e = ent[i];
        float4 v1 = *(const float4*)(b1 + c);
        float4 v2 = *(const float4*)(b2 + c);
        float4 x1 = h1[i];
        float4 x2 = h2[i];
        out[i] = make_float4(e.x+v1.x+v2.x + w1*x1.x + w2*x2.x,
                             e.y+v1.y+v2.y + w1*x1.y + w2*x2.y,
                             e.z+v1.z+v2.z + w1*x1.z + w2*x2.z,
                             e.w+v1.w+v2.w + w1*x1.w + w2*x2.w);
    }
}
// warp per edge: out[d] += w1*h1[s] + w2*h2[s]   (fused GAT1+GAT2 aggregation)
__global__ void k_gat2_edge(const int2* __restrict__ ed,
                            const float* __restrict__ h1, const float* __restrict__ h2,
                            float* __restrict__ out, int E){
    int g = blockIdx.x*blockDim.x + threadIdx.x;
    int lane = g & 31, e = g >> 5;
    if (e >= E) return;
    int2 sd = ed[e];
    float2 a = g_alpha2[e]; uint2 m = g_m2[sd.y]; float2 z = g_z2[sd.y];
    float w1 = __expf(a.x - ord2f(m.x)) / (z.x + 1e-16f);
    float w2 = __expf(a.y - ord2f(m.y)) / (z.y + 1e-16f);
    float4 x1 = *(const float4*)(h1 + (size_t)sd.x*D + lane*4);
    float4 x2 = *(const float4*)(h2 + (size_t)sd.x*D + lane*4);
    red4(out + (size_t)sd.y*D + lane*4,
         make_float4(w1*x1.x + w2*x2.x, w1*x1.y + w2*x2.y,
                     w1*x1.z + w2*x2.z, w1*x1.w + w2*x2.w));
}

// ---------------- launcher ----------------
extern "C" void kernel_launch(void* const* d_in, const int* in_sizes, int n_in,
                              void* d_out, int out_size)
{
    const int*   triples  = (const int*)  d_in[0];
    const int2*  ent_ed   = (const int2*) d_in[1];
    const float* ent_lab  = (const float*)d_in[2];
    const int2*  val_ed   = (const int2*) d_in[3];
    const float* att      = (const float*)d_in[5];
    const float* valf     = (const float*)d_in[6];
    const float* entf     = (const float*)d_in[7];
    const float* Wp       = (const float*)d_in[8];
    const float* g1W      = (const float*)d_in[9];
    const float* g1b      = (const float*)d_in[10];
    const float* g2W      = (const float*)d_in[11];
    const float* g2b      = (const float*)d_in[12];
    const float* Wl1      = (const float*)d_in[13];
    const float* as1      = (const float*)d_in[14];
    const float* ad1      = (const float*)d_in[15];
    const float* We1      = (const float*)d_in[16];
    const float* ae1      = (const float*)d_in[17];
    const float* gb1      = (const float*)d_in[18];
    const float* Wl2      = (const float*)d_in[19];
    const float* as2      = (const float*)d_in[20];
    const float* ad2      = (const float*)d_in[21];
    const float* We2      = (const float*)d_in[22];
    const float* ae2      = (const float*)d_in[23];
    const float* gb2      = (const float*)d_in[24];

    const int T   = in_sizes[0] / 3;
    const int E1  = in_sizes[1] / 2;
    const int E2  = in_sizes[3] / 2;
    const int NE  = in_sizes[7] / D;   // num_ent
    const int N   = NE + T;
    float* out = (float*)d_out;

    float *nodesA, *nodesB, *hbuf, *dinv, *lattr;
    int *deg, *cnt;
    cudaGetSymbolAddress((void**)&nodesA, g_nodesA);
    cudaGetSymbolAddress((void**)&nodesB, g_nodesB);
    cudaGetSymbolAddress((void**)&hbuf,   g_hbuf);
    cudaGetSymbolAddress((void**)&dinv,   g_dinv);
    cudaGetSymbolAddress((void**)&deg,    g_deg);
    cudaGetSymbolAddress((void**)&cnt,    g_cnt);
    cudaGetSymbolAddress((void**)&lattr,  g_lattr);

    const int TB = 256;
    #define GRID1(n) (((n) + TB - 1) / TB)

    // ---- build node features ----
    k_copy4 <<<GRID1(NE*32), TB>>>((const float4*)entf, (float4*)nodesA, NE*32);
    k_valenc<<<(T + 127)/128, TB>>>(triples, att, valf, Wp, nodesA + (size_t)NE*D, T);

    // ---- degree / norm for GCN ----
    k_seti  <<<GRID1(N), TB>>>(deg, 1, N);
    k_deg_acc<<<GRID1(E2), TB>>>(val_ed, deg, E2);
    k_dinv  <<<GRID1(N), TB>>>(deg, dinv, N);

    // ---- GCN layer 1 (full N output needed) ----
    k_gemm128 <<<(N + 127)/128, TB>>>(nodesA, g1W, hbuf, N);
    k_self_gcn<<<GRID1(N*32), TB>>>((const float4*)hbuf, dinv, g1b, (float4*)nodesB, N);
    k_gcn_edge<<<(E2 + 7)/8, TB>>>(val_ed, hbuf, dinv, nodesB, E2, N);

    // ---- GCN layer 2 (only entity rows consumed downstream) ----
    k_gemm128 <<<(N + 127)/128, TB>>>(nodesB, g2W, hbuf, N);
    k_self_gcn<<<GRID1(NE*32), TB>>>((const float4*)hbuf, dinv, g2b, (float4*)nodesA, NE);
    k_gcn_edge<<<(E2 + 7)/8, TB>>>(val_ed, hbuf, dinv, nodesA, E2, NE);

    // ---- GAT prep ----
    k_seti <<<GRID1(NE), TB>>>(cnt, 0, NE);
    k_setf <<<GRID1(NE), TB>>>(lattr, 0.f, NE);
    k_cnt  <<<GRID1(E1), TB>>>(ent_ed, ent_lab, cnt, lattr, E1);
    k_lattr<<<GRID1(NE), TB>>>(cnt, lattr, NE);

    // ---- fused GAT1+GAT2 ----
    float* h1 = hbuf;
    float* h2 = hbuf + (size_t)NE*D;
    k_gemm128<<<(NE + 127)/128, TB>>>(nodesA, Wl1, h1, NE);
    k_gemm128<<<(NE + 127)/128, TB>>>(nodesA, Wl2, h2, NE);
    k_ce2    <<<1, 64>>>(We1, ae1, We2, ae2);
    k_att_fused<<<(NE + 7)/8, TB>>>(h1, h2, as1, ad1, as2, ad2, lattr, NE);
    k_alpha2 <<<GRID1(E1), TB>>>(ent_ed, ent_lab, E1);
    k_z2init <<<GRID1(NE), TB>>>(NE);
    k_z2acc  <<<GRID1(E1), TB>>>(ent_ed, E1);
    k_self2  <<<GRID1(NE*32), TB>>>((const float4*)entf, gb1, gb2,
                                    (const float4*)h1, (const float4*)h2, (float4*)out, NE);
    k_gat2_edge<<<(E1 + 7)/8, TB>>>(ent_ed, h1, h2, out, E1);
    #undef GRID1
}

// round 4
// speedup vs baseline: 1.8733x; 1.4633x over previous
#include <cuda_runtime.h>
#include <cuda_bf16.h>
#include <math.h>
#include <stdint.h>

#define D 128
#define MAX_N   400000
#define MAX_E1  1000000
#define MAX_ENT 150000

// ---------------- device scratch (no allocs allowed) ----------------
__device__ float    g_nodesA[(size_t)MAX_N * D];
__device__ float    g_nodesB[(size_t)MAX_N * D];
__device__ float    g_hbuf  [(size_t)MAX_N * D];
__device__ float    g_dinv  [MAX_N];
__device__ int      g_deg   [MAX_N];
__device__ float2   g_als2  [MAX_ENT];
__device__ float2   g_ald2  [MAX_ENT];
__device__ float2   g_aself2[MAX_ENT];
__device__ uint2    g_m2    [MAX_ENT];
__device__ float2   g_z2    [MAX_ENT];
__device__ int      g_cnt   [MAX_ENT];
__device__ float    g_lattr [MAX_ENT];
__device__ float2   g_alpha2[MAX_E1];
__device__ float    g_ce2[2];
__device__ float    g_zerovec[D];   // stays zero

// ---------------- small helpers ----------------
__device__ __forceinline__ unsigned f2ord(float f){
    unsigned u = __float_as_uint(f);
    return (u & 0x80000000u) ? ~u : (u | 0x80000000u);
}
__device__ __forceinline__ float ord2f(unsigned u){
    return __uint_as_float((u & 0x80000000u) ? (u ^ 0x80000000u) : ~u);
}
__device__ __forceinline__ float lrelu(float x){ return x > 0.f ? x : 0.2f * x; }
__device__ __forceinline__ void red4(float* p, float4 v){
    asm volatile("red.global.add.v4.f32 [%0], {%1,%2,%3,%4};"
        :: "l"(p), "f"(v.x), "f"(v.y), "f"(v.z), "f"(v.w) : "memory");
}
__device__ __forceinline__ uint32_t smem_u32(const void* p){
    uint32_t a; asm("{ .reg .u64 t; cvta.to.shared.u64 t, %1; cvt.u32.u64 %0, t; }" : "=r"(a) : "l"(p));
    return a;
}

// ---------------- mma.sync bf16x3 GEMM ----------------
// smem: 4 arrays of [128 rows][136 bf16] (hi/lo for A and B), stride 136 => conflict-free
#define ASTR   136
#define AS_HI  0u
#define AS_LO  34816u
#define BS_HI  69632u
#define BS_LO  104448u
#define SMEM_MMA 139264

__device__ __forceinline__ void ldsm4(uint32_t (&r)[4], uint32_t addr){
    asm volatile("ldmatrix.sync.aligned.m8n8.x4.shared.b16 {%0,%1,%2,%3}, [%4];"
        : "=r"(r[0]), "=r"(r[1]), "=r"(r[2]), "=r"(r[3]) : "r"(addr));
}
__device__ __forceinline__ void ldsm4t(uint32_t &r0, uint32_t &r1, uint32_t &r2, uint32_t &r3, uint32_t addr){
    asm volatile("ldmatrix.sync.aligned.m8n8.x4.trans.shared.b16 {%0,%1,%2,%3}, [%4];"
        : "=r"(r0), "=r"(r1), "=r"(r2), "=r"(r3) : "r"(addr));
}
__device__ __forceinline__ void mma_bf16(float (&d)[4], const uint32_t (&a)[4], uint32_t b0, uint32_t b1){
    asm volatile("mma.sync.aligned.m16n8k16.row.col.f32.bf16.bf16.f32 "
        "{%0,%1,%2,%3}, {%4,%5,%6,%7}, {%8,%9}, {%0,%1,%2,%3};"
        : "+f"(d[0]), "+f"(d[1]), "+f"(d[2]), "+f"(d[3])
        : "r"(a[0]), "r"(a[1]), "r"(a[2]), "r"(a[3]), "r"(b0), "r"(b1));
}
// fragment-load address: row-major [128][ASTR] bf16 array at shared byte base `arr`
__device__ __forceinline__ uint32_t frag_addr(uint32_t arr, int row0, int col0, int lane){
    int grp = lane >> 3, lr = lane & 7;
    int r = row0 + (grp & 1)*8 + lr;
    int c = col0 + (grp >> 1)*8;
    return arr + (uint32_t)(r*ASTR + c)*2u;
}
// convert float4 -> bf16 hi/lo and store 8B each
__device__ __forceinline__ void stage4(char* sm, uint32_t off_hi, uint32_t off_lo,
                                       int r, int c4, float4 v){
    __nv_bfloat16 h0 = __float2bfloat16_rn(v.x), h1 = __float2bfloat16_rn(v.y),
                  h2 = __float2bfloat16_rn(v.z), h3 = __float2bfloat16_rn(v.w);
    __nv_bfloat16 l0 = __float2bfloat16_rn(v.x - __bfloat162float(h0));
    __nv_bfloat16 l1 = __float2bfloat16_rn(v.y - __bfloat162float(h1));
    __nv_bfloat16 l2 = __float2bfloat16_rn(v.z - __bfloat162float(h2));
    __nv_bfloat16 l3 = __float2bfloat16_rn(v.w - __bfloat162float(h3));
    __nv_bfloat162 hp0, hp1, lp0, lp1;
    hp0.x = h0; hp0.y = h1; hp1.x = h2; hp1.y = h3;
    lp0.x = l0; lp0.y = l1; lp1.x = l2; lp1.y = l3;
    uint32_t byt = (uint32_t)(r*ASTR + c4*4)*2u;
    uint2 uh, ul;
    uh.x = *(uint32_t*)&hp0; uh.y = *(uint32_t*)&hp1;
    ul.x = *(uint32_t*)&lp0; ul.y = *(uint32_t*)&lp1;
    *(uint2*)(sm + off_hi + byt) = uh;
    *(uint2*)(sm + off_lo + byt) = ul;
}

// core compute over staged 128x128 slab: acc += As @ Bs^T(hi/lo 3-term)
__device__ __forceinline__ void mma_slab(uint32_t smb, int wm, int n0, int lane,
                                         float (&acc)[2][8][4]){
#pragma unroll
    for (int kt = 0; kt < 8; ++kt){
        int k0 = kt*16;
        uint32_t ah[2][4], al[2][4], bh[8][2], bl[8][2];
#pragma unroll
        for (int mt = 0; mt < 2; ++mt){
            uint32_t adr = frag_addr(smb + AS_HI, wm*32 + mt*16, k0, lane);
            ldsm4(ah[mt], adr);
            ldsm4(al[mt], adr + (AS_LO - AS_HI));
        }
#pragma unroll
        for (int nb = 0; nb < 4; ++nb){
            uint32_t adr = frag_addr(smb + BS_HI, k0, n0 + nb*16, lane);
            ldsm4t(bh[2*nb][0], bh[2*nb][1], bh[2*nb+1][0], bh[2*nb+1][1], adr);
            ldsm4t(bl[2*nb][0], bl[2*nb][1], bl[2*nb+1][0], bl[2*nb+1][1],
                   adr + (BS_LO - BS_HI));
        }
#pragma unroll
        for (int mt = 0; mt < 2; ++mt)
#pragma unroll
            for (int nt = 0; nt < 8; ++nt){
                mma_bf16(acc[mt][nt], ah[mt], bh[nt][0], bh[nt][1]);
                mma_bf16(acc[mt][nt], ah[mt], bl[nt][0], bl[nt][1]);
                mma_bf16(acc[mt][nt], al[mt], bh[nt][0], bh[nt][1]);
            }
    }
}

// C[M,128] = A[M,128] @ B[128,128]; optional bias into C; optional fused
// self-gcn second output: self_out[r] = bias2 + dinv[r]^2 * val (C gets raw val)
__global__ void __launch_bounds__(256, 1) k_gemm_mma(const float* __restrict__ A,
    const float* __restrict__ Bw, float* __restrict__ C, const float* __restrict__ bias,
    float* __restrict__ self_out, const float* __restrict__ bias2,
    const float* __restrict__ dinv, int M)
{
    extern __shared__ char sm[];
    const uint32_t smb = smem_u32(sm);
    const int tid = threadIdx.x, lane = tid & 31, wid = tid >> 5;
    const int wm = wid & 3, n0 = (wid >> 2)*64;
    const int m0 = blockIdx.x * 128;

#pragma unroll
    for (int i = 0; i < 16; ++i){
        int f = tid + i*256, r = f >> 5, c4 = f & 31;
        int row = m0 + r; if (row >= M) row = M - 1;
        stage4(sm, AS_HI, AS_LO, r, c4, *(const float4*)(A + (size_t)row*D + c4*4));
    }
#pragma unroll
    for (int i = 0; i < 16; ++i){
        int f = tid + i*256, r = f >> 5, c4 = f & 31;
        stage4(sm, BS_HI, BS_LO, r, c4, *(const float4*)(Bw + (size_t)r*D + c4*4));
    }
    __syncthreads();

    float acc[2][8][4];
#pragma unroll
    for (int mt = 0; mt < 2; ++mt)
#pragma unroll
        for (int nt = 0; nt < 8; ++nt)
#pragma unroll
            for (int j = 0; j < 4; ++j) acc[mt][nt][j] = 0.f;

    mma_slab(smb, wm, n0, lane, acc);

#pragma unroll
    for (int mt = 0; mt < 2; ++mt)
#pragma unroll
        for (int nt = 0; nt < 8; ++nt){
            int r = m0 + wm*32 + mt*16 + (lane >> 2);
            int c = n0 + nt*8 + (lane & 3)*2;
            float b0 = bias ? bias[c] : 0.f, b1 = bias ? bias[c+1] : 0.f;
            float d0 = acc[mt][nt][0], d1 = acc[mt][nt][1];
            float d2 = acc[mt][nt][2], d3 = acc[mt][nt][3];
            if (r < M){
                *(float2*)(C + (size_t)r*D + c) = make_float2(d0 + b0, d1 + b1);
                if (self_out){
                    float s = dinv[r]; s *= s;
                    *(float2*)(self_out + (size_t)r*D + c) =
                        make_float2(bias2[c] + s*d0, bias2[c+1] + s*d1);
                }
            }
            if (r + 8 < M){
                *(float2*)(C + (size_t)(r+8)*D + c) = make_float2(d2 + b0, d3 + b1);
                if (self_out){
                    float s = dinv[r+8]; s *= s;
                    *(float2*)(self_out + (size_t)(r+8)*D + c) =
                        make_float2(bias2[c] + s*d2, bias2[c+1] + s*d3);
                }
            }
        }
}

// C[t,:] = concat(att[a_t], val[v_t]) @ W (K=256), two staged phases
__global__ void __launch_bounds__(256, 1) k_valenc_mma(const int* __restrict__ triples,
    const float* __restrict__ att, const float* __restrict__ val,
    const float* __restrict__ W, float* __restrict__ C, int T)
{
    extern __shared__ char sm[];
    __shared__ int idxA[128], idxV[128];
    const uint32_t smb = smem_u32(sm);
    const int tid = threadIdx.x, lane = tid & 31, wid = tid >> 5;
    const int wm = wid & 3, n0 = (wid >> 2)*64;
    const int m0 = blockIdx.x * 128;
    if (tid < 128){
        int t = m0 + tid; if (t >= T) t = T - 1;
        idxV[tid] = triples[3*t + 1];
        idxA[tid] = triples[3*t + 2];
    }
    __syncthreads();

    float acc[2][8][4];
#pragma unroll
    for (int mt = 0; mt < 2; ++mt)
#pragma unroll
        for (int nt = 0; nt < 8; ++nt)
#pragma unroll
            for (int j = 0; j < 4; ++j) acc[mt][nt][j] = 0.f;

    for (int ph = 0; ph < 2; ++ph){
        if (ph) __syncthreads();
#pragma unroll
        for (int i = 0; i < 16; ++i){
            int f = tid + i*256, r = f >> 5, c4 = f & 31;
            const float* src = ph ? (val + (size_t)idxV[r]*D) : (att + (size_t)idxA[r]*D);
            stage4(sm, AS_HI, AS_LO, r, c4, *(const float4*)(src + c4*4));
        }
        const float* Wph = W + (size_t)ph*128*D;
#pragma unroll
        for (int i = 0; i < 16; ++i){
            int f = tid + i*256, r = f >> 5, c4 = f & 31;
            stage4(sm, BS_HI, BS_LO, r, c4, *(const float4*)(Wph + (size_t)r*D + c4*4));
        }
        __syncthreads();
        mma_slab(smb, wm, n0, lane, acc);
    }

#pragma unroll
    for (int mt = 0; mt < 2; ++mt)
#pragma unroll
        for (int nt = 0; nt < 8; ++nt){
            int r = m0 + wm*32 + mt*16 + (lane >> 2);
            int c = n0 + nt*8 + (lane & 3)*2;
            if (r < T)
                *(float2*)(C + (size_t)r*D + c) = make_float2(acc[mt][nt][0], acc[mt][nt][1]);
            if (r + 8 < T)
                *(float2*)(C + (size_t)(r+8)*D + c) = make_float2(acc[mt][nt][2], acc[mt][nt][3]);
        }
}

// ---------------- elementwise / edge kernels ----------------
__global__ void k_copy4(const float4* __restrict__ s, float4* __restrict__ d, int n){
    int i = blockIdx.x*blockDim.x + threadIdx.x;
    if (i < n) d[i] = s[i];
}
__global__ void k_seti(int* p, int v, int n){
    int i = blockIdx.x*blockDim.x + threadIdx.x; if (i < n) p[i] = v;
}
__global__ void k_setf(float* p, float v, int n){
    int i = blockIdx.x*blockDim.x + threadIdx.x; if (i < n) p[i] = v;
}
__global__ void k_deg_acc(const int2* __restrict__ ed, int* deg, int E){
    int i = blockIdx.x*blockDim.x + threadIdx.x;
    if (i < E) atomicAdd(deg + ed[i].y, 1);
}
__global__ void k_dinv(const int* __restrict__ deg, float* __restrict__ dinv, int n){
    int i = blockIdx.x*blockDim.x + threadIdx.x;
    if (i < n) dinv[i] = rsqrtf((float)deg[i]);
}
__global__ void k_self_gcn(const float4* __restrict__ h, const float* __restrict__ dinv,
                           const float* __restrict__ b, float4* __restrict__ out, int M){
    int i = blockIdx.x*blockDim.x + threadIdx.x;
    if (i < M*32){
        int j = i >> 5, c = (i & 31)*4;
        float s = dinv[j]; s *= s;
        float4 hv = h[i];
        float4 bv = *(const float4*)(b + c);
        out[i] = make_float4(bv.x + s*hv.x, bv.y + s*hv.y, bv.z + s*hv.z, bv.w + s*hv.w);
    }
}
__global__ void k_gcn_edge(const int2* __restrict__ ed, const float* __restrict__ h,
                           const float* __restrict__ dinv, float* __restrict__ out, int E, int maxd){
    int g = blockIdx.x*blockDim.x + threadIdx.x;
    int lane = g & 31, e = g >> 5;
    if (e >= E) return;
    int2 sd = ed[e];
    if (sd.y >= maxd) return;
    float nrm = dinv[sd.x]*dinv[sd.y];
    float4 hv = *(const float4*)(h + (size_t)sd.x*D + lane*4);
    red4(out + (size_t)sd.y*D + lane*4,
         make_float4(nrm*hv.x, nrm*hv.y, nrm*hv.z, nrm*hv.w));
}
__global__ void k_cnt(const int2* __restrict__ ed, const float* __restrict__ lab,
                      int* cnt, float* ls, int E){
    int i = blockIdx.x*blockDim.x + threadIdx.x;
    if (i < E){ int d = ed[i].y; atomicAdd(cnt + d, 1); atomicAdd(ls + d, lab[i]); }
}
__global__ void k_lattr(const int* __restrict__ cnt, float* __restrict__ ls, int n){
    int i = blockIdx.x*blockDim.x + threadIdx.x;
    if (i < n) ls[i] = ls[i] / fmaxf((float)cnt[i], 1.f);
}
__global__ void k_ce2(const float* __restrict__ We1, const float* __restrict__ ae1,
                      const float* __restrict__ We2, const float* __restrict__ ae2){
    int t = threadIdx.x;
    int lane = t & 31, w = t >> 5;
    const float* We = w ? We2 : We1;
    const float* ae = w ? ae2 : ae1;
    float s = 0.f;
    for (int i = lane; i < D; i += 32) s += We[i]*ae[i];
#pragma unroll
    for (int o = 16; o; o >>= 1) s += __shfl_xor_sync(0xffffffffu, s, o);
    if (lane == 0) g_ce2[w] = s;
}
__global__ void k_att_fused(const float* __restrict__ h1, const float* __restrict__ h2,
    const float* __restrict__ as1, const float* __restrict__ ad1,
    const float* __restrict__ as2, const float* __restrict__ ad2,
    const float* __restrict__ lattr, int M)
{
    int g = blockIdx.x*blockDim.x + threadIdx.x;
    int lane = g & 31, row = g >> 5;
    if (row >= M) return;
    float4 h1v = *(const float4*)(h1 + (size_t)row*D + lane*4);
    float4 h2v = *(const float4*)(h2 + (size_t)row*D + lane*4);
    float4 s1 = *(const float4*)(as1 + lane*4);
    float4 d1 = *(const float4*)(ad1 + lane*4);
    float4 s2 = *(const float4*)(as2 + lane*4);
    float4 d2 = *(const float4*)(ad2 + lane*4);
    float x1 = h1v.x*s1.x + h1v.y*s1.y + h1v.z*s1.z + h1v.w*s1.w;
    float y1 = h1v.x*d1.x + h1v.y*d1.y + h1v.z*d1.z + h1v.w*d1.w;
    float x2 = h2v.x*s2.x + h2v.y*s2.y + h2v.z*s2.z + h2v.w*s2.w;
    float y2 = h2v.x*d2.x + h2v.y*d2.y + h2v.z*d2.z + h2v.w*d2.w;
#pragma unroll
    for (int o = 16; o; o >>= 1){
        x1 += __shfl_xor_sync(0xffffffffu, x1, o);
        y1 += __shfl_xor_sync(0xffffffffu, y1, o);
        x2 += __shfl_xor_sync(0xffffffffu, x2, o);
        y2 += __shfl_xor_sync(0xffffffffu, y2, o);
    }
    if (lane == 0){
        float la = lattr[row];
        g_als2[row] = make_float2(x1, x2);
        g_ald2[row] = make_float2(y1, y2);
        float a1 = lrelu(x1 + y1 + la*g_ce2[0]);
        float a2 = lrelu(x2 + y2 + la*g_ce2[1]);
        g_aself2[row] = make_float2(a1, a2);
        g_m2[row] = make_uint2(f2ord(a1), f2ord(a2));
    }
}
__global__ void k_alpha2(const int2* __restrict__ ed, const float* __restrict__ lab, int E){
    int i = blockIdx.x*blockDim.x + threadIdx.x;
    if (i >= E) return;
    int2 sd = ed[i];
    float2 als = g_als2[sd.x];
    float2 ald = g_ald2[sd.y];
    float la = lab[i];
    float a1 = lrelu(als.x + ald.x + la*g_ce2[0]);
    float a2 = lrelu(als.y + ald.y + la*g_ce2[1]);
    g_alpha2[i] = make_float2(a1, a2);
    atomicMax(&g_m2[sd.y].x, f2ord(a1));
    atomicMax(&g_m2[sd.y].y, f2ord(a2));
}
__global__ void k_z2init(int n){
    int i = blockIdx.x*blockDim.x + threadIdx.x;
    if (i < n){
        float2 a = g_aself2[i]; uint2 m = g_m2[i];
        g_z2[i] = make_float2(__expf(a.x - ord2f(m.x)), __expf(a.y - ord2f(m.y)));
    }
}
__global__ void k_z2acc(const int2* __restrict__ ed, int E){
    int i = blockIdx.x*blockDim.x + threadIdx.x;
    if (i >= E) return;
    int d = ed[i].y;
    float2 a = g_alpha2[i]; uint2 m = g_m2[d];
    atomicAdd(&g_z2[d].x, __expf(a.x - ord2f(m.x)));
    atomicAdd(&g_z2[d].y, __expf(a.y - ord2f(m.y)));
}
__global__ void k_self2(const float4* __restrict__ ent, const float* __restrict__ b1,
                        const float* __restrict__ b2, const float4* __restrict__ h1,
                        const float4* __restrict__ h2, float4* __restrict__ out, int M){
    int i = blockIdx.x*blockDim.x + threadIdx.x;
    if (i < M*32){
        int j = i >> 5, c = (i & 31)*4;
        float2 a = g_aself2[j]; uint2 m = g_m2[j]; float2 z = g_z2[j];
        float w1 = __expf(a.x - ord2f(m.x)) / (z.x + 1e-16f);
        float w2 = __expf(a.y - ord2f(m.y)) / (z.y + 1e-16f);
        float4 e = ent[i];
        float4 v1 = *(const float4*)(b1 + c);
        float4 v2 = *(const float4*)(b2 + c);
        float4 x1 = h1[i];
        float4 x2 = h2[i];
        out[i] = make_float4(e.x+v1.x+v2.x + w1*x1.x + w2*x2.x,
                             e.y+v1.y+v2.y + w1*x1.y + w2*x2.y,
                             e.z+v1.z+v2.z + w1*x1.z + w2*x2.z,
                             e.w+v1.w+v2.w + w1*x1.w + w2*x2.w);
    }
}
__global__ void k_gat2_edge(const int2* __restrict__ ed,
                            const float* __restrict__ h1, const float* __restrict__ h2,
                            float* __restrict__ out, int E){
    int g = blockIdx.x*blockDim.x + threadIdx.x;
    int lane = g & 31, e = g >> 5;
    if (e >= E) return;
    int2 sd = ed[e];
    float2 a = g_alpha2[e]; uint2 m = g_m2[sd.y]; float2 z = g_z2[sd.y];
    float w1 = __expf(a.x - ord2f(m.x)) / (z.x + 1e-16f);
    float w2 = __expf(a.y - ord2f(m.y)) / (z.y + 1e-16f);
    float4 x1 = *(const float4*)(h1 + (size_t)sd.x*D + lane*4);
    float4 x2 = *(const float4*)(h2 + (size_t)sd.x*D + lane*4);
    red4(out + (size_t)sd.y*D + lane*4,
         make_float4(w1*x1.x + w2*x2.x, w1*x1.y + w2*x2.y,
                     w1*x1.z + w2*x2.z, w1*x1.w + w2*x2.w));
}

// ---------------- launcher ----------------
extern "C" void kernel_launch(void* const* d_in, const int* in_sizes, int n_in,
                              void* d_out, int out_size)
{
    const int*   triples  = (const int*)  d_in[0];
    const int2*  ent_ed   = (const int2*) d_in[1];
    const float* ent_lab  = (const float*)d_in[2];
    const int2*  val_ed   = (const int2*) d_in[3];
    const float* att      = (const float*)d_in[5];
    const float* valf     = (const float*)d_in[6];
    const float* entf     = (const float*)d_in[7];
    const float* Wp       = (const float*)d_in[8];
    const float* g1W      = (const float*)d_in[9];
    const float* g1b      = (const float*)d_in[10];
    const float* g2W      = (const float*)d_in[11];
    const float* g2b      = (const float*)d_in[12];
    const float* Wl1      = (const float*)d_in[13];
    const float* as1      = (const float*)d_in[14];
    const float* ad1      = (const float*)d_in[15];
    const float* We1      = (const float*)d_in[16];
    const float* ae1      = (const float*)d_in[17];
    const float* gb1      = (const float*)d_in[18];
    const float* Wl2      = (const float*)d_in[19];
    const float* as2      = (const float*)d_in[20];
    const float* ad2      = (const float*)d_in[21];
    const float* We2      = (const float*)d_in[22];
    const float* ae2      = (const float*)d_in[23];
    const float* gb2      = (const float*)d_in[24];

    const int T   = in_sizes[0] / 3;
    const int E1  = in_sizes[1] / 2;
    const int E2  = in_sizes[3] / 2;
    const int NE  = in_sizes[7] / D;
    const int N   = NE + T;
    float* out = (float*)d_out;

    float *nodesA, *nodesB, *hbuf, *dinv, *lattr, *zerov;
    int *deg, *cnt;
    cudaGetSymbolAddress((void**)&nodesA, g_nodesA);
    cudaGetSymbolAddress((void**)&nodesB, g_nodesB);
    cudaGetSymbolAddress((void**)&hbuf,   g_hbuf);
    cudaGetSymbolAddress((void**)&dinv,   g_dinv);
    cudaGetSymbolAddress((void**)&deg,    g_deg);
    cudaGetSymbolAddress((void**)&cnt,    g_cnt);
    cudaGetSymbolAddress((void**)&lattr,  g_lattr);
    cudaGetSymbolAddress((void**)&zerov,  g_zerovec);

    cudaFuncSetAttribute(k_gemm_mma,   cudaFuncAttributeMaxDynamicSharedMemorySize, SMEM_MMA);
    cudaFuncSetAttribute(k_valenc_mma, cudaFuncAttributeMaxDynamicSharedMemorySize, SMEM_MMA);

    const int TB = 256;
    #define GRID1(n) (((n) + TB - 1) / TB)

    // ---- build node features ----
    k_copy4 <<<GRID1(NE*32), TB>>>((const float4*)entf, (float4*)nodesA, NE*32);
    k_valenc_mma<<<(T + 127)/128, TB, SMEM_MMA>>>(triples, att, valf, Wp,
                                                  nodesA + (size_t)NE*D, T);
    // ---- degree / norm ----
    k_seti  <<<GRID1(N), TB>>>(deg, 1, N);
    k_deg_acc<<<GRID1(E2), TB>>>(val_ed, deg, E2);
    k_dinv  <<<GRID1(N), TB>>>(deg, dinv, N);

    // ---- GCN layer 1 (transform-first, full N; self-loop fused into epilogue) ----
    k_gemm_mma<<<(N + 127)/128, TB, SMEM_MMA>>>(nodesA, g1W, hbuf,
                                                (const float*)0, nodesB, g1b, dinv, N);
    k_gcn_edge<<<(E2 + 7)/8, TB>>>(val_ed, hbuf, dinv, nodesB, E2, N);

    // ---- GCN layer 2 (aggregate-first: only NE output rows) ----
    k_self_gcn<<<GRID1(NE*32), TB>>>((const float4*)nodesB, dinv, zerov, (float4*)nodesA, NE);
    k_gcn_edge<<<(E2 + 7)/8, TB>>>(val_ed, nodesB, dinv, nodesA, E2, NE);
    k_gemm_mma<<<(NE + 127)/128, TB, SMEM_MMA>>>(nodesA, g2W, hbuf, g2b,
                                                 (float*)0, (const float*)0, (const float*)0, NE);

    // ---- GAT prep ----
    k_seti <<<GRID1(NE), TB>>>(cnt, 0, NE);
    k_setf <<<GRID1(NE), TB>>>(lattr, 0.f, NE);
    k_cnt  <<<GRID1(E1), TB>>>(ent_ed, ent_lab, cnt, lattr, E1);
    k_lattr<<<GRID1(NE), TB>>>(cnt, lattr, NE);

    // ---- fused GAT1+GAT2 ----
    float* h1 = nodesA;
    float* h2 = nodesB;
    k_gemm_mma<<<(NE + 127)/128, TB, SMEM_MMA>>>(hbuf, Wl1, h1, (const float*)0,
                                                 (float*)0, (const float*)0, (const float*)0, NE);
    k_gemm_mma<<<(NE + 127)/128, TB, SMEM_MMA>>>(hbuf, Wl2, h2, (const float*)0,
                                                 (float*)0, (const float*)0, (const float*)0, NE);
    k_ce2    <<<1, 64>>>(We1, ae1, We2, ae2);
    k_att_fused<<<(NE + 7)/8, TB>>>(h1, h2, as1, ad1, as2, ad2, lattr, NE);
    k_alpha2 <<<GRID1(E1), TB>>>(ent_ed, ent_lab, E1);
    k_z2init <<<GRID1(NE), TB>>>(NE);
    k_z2acc  <<<GRID1(E1), TB>>>(ent_ed, E1);
    k_self2  <<<GRID1(NE*32), TB>>>((const float4*)entf, gb1, gb2,
                                    (const float4*)h1, (const float4*)h2, (float4*)out, NE);
    k_gat2_edge<<<(E1 + 7)/8, TB>>>(ent_ed, h1, h2, out, E1);
    #undef GRID1
}

// round 5
// speedup vs baseline: 2.0569x; 1.0980x over previous
#include <cuda_runtime.h>
#include <cuda_bf16.h>
#include <math.h>
#include <stdint.h>

#define D 128
#define MAX_N   400000
#define MAX_E1  1000000
#define MAX_ENT 150000

// ---------------- device scratch (no allocs allowed) ----------------
__device__ float    g_nodesA[(size_t)MAX_N * D];
__device__ float    g_nodesB[(size_t)MAX_N * D];
__device__ float    g_hbuf  [(size_t)MAX_N * D];
__device__ float    g_dinv  [MAX_N];
__device__ int      g_deg   [MAX_N];
__device__ float2   g_als2  [MAX_ENT];
__device__ float2   g_ald2  [MAX_ENT];
__device__ float2   g_eself2[MAX_ENT];   // exp(alpha_self)
__device__ float2   g_z2    [MAX_ENT];
__device__ int      g_cnt   [MAX_ENT];
__device__ float    g_lattr [MAX_ENT];
__device__ float2   g_exp2  [MAX_E1];    // exp(alpha_edge) both layers
__device__ float    g_ce2[2];
__device__ float    g_zerovec[D];        // stays zero

// ---------------- small helpers ----------------
__device__ __forceinline__ float lrelu(float x){ return x > 0.f ? x : 0.2f * x; }
__device__ __forceinline__ void red4(float* p, float4 v){
    asm volatile("red.global.add.v4.f32 [%0], {%1,%2,%3,%4};"
        :: "l"(p), "f"(v.x), "f"(v.y), "f"(v.z), "f"(v.w) : "memory");
}
__device__ __forceinline__ void red2(float* p, float2 v){
    asm volatile("red.global.add.v2.f32 [%0], {%1,%2};"
        :: "l"(p), "f"(v.x), "f"(v.y) : "memory");
}
__device__ __forceinline__ uint32_t smem_u32(const void* p){
    uint32_t a; asm("{ .reg .u64 t; cvta.to.shared.u64 t, %1; cvt.u32.u64 %0, t; }" : "=r"(a) : "l"(p));
    return a;
}

// ---------------- mma.sync bf16x3 GEMM (64-row M tiles, occ 2) ----------------
// smem: A hi/lo [64][136] bf16, B hi/lo [128][136] bf16 => 104448 bytes
#define ASTR   136
#define AS_HI  0u
#define AS_LO  17408u
#define BS_HI  34816u
#define BS_LO  104448u     // placed after B_HI block (B_HI is 128 rows)
// layout: AS_HI [64*136*2=17408], AS_LO [17408], BS_HI [128*136*2=34816], BS_LO [34816]
#undef  BS_LO
#define BS_HI2 34816u
#define BS_LO2 69632u
#define SMEM_MMA 104448

__device__ __forceinline__ void ldsm4(uint32_t (&r)[4], uint32_t addr){
    asm volatile("ldmatrix.sync.aligned.m8n8.x4.shared.b16 {%0,%1,%2,%3}, [%4];"
        : "=r"(r[0]), "=r"(r[1]), "=r"(r[2]), "=r"(r[3]) : "r"(addr));
}
__device__ __forceinline__ void ldsm4t(uint32_t &r0, uint32_t &r1, uint32_t &r2, uint32_t &r3, uint32_t addr){
    asm volatile("ldmatrix.sync.aligned.m8n8.x4.trans.shared.b16 {%0,%1,%2,%3}, [%4];"
        : "=r"(r0), "=r"(r1), "=r"(r2), "=r"(r3) : "r"(addr));
}
__device__ __forceinline__ void mma_bf16(float (&d)[4], const uint32_t (&a)[4], uint32_t b0, uint32_t b1){
    asm volatile("mma.sync.aligned.m16n8k16.row.col.f32.bf16.bf16.f32 "
        "{%0,%1,%2,%3}, {%4,%5,%6,%7}, {%8,%9}, {%0,%1,%2,%3};"
        : "+f"(d[0]), "+f"(d[1]), "+f"(d[2]), "+f"(d[3])
        : "r"(a[0]), "r"(a[1]), "r"(a[2]), "r"(a[3]), "r"(b0), "r"(b1));
}
__device__ __forceinline__ uint32_t frag_addr(uint32_t arr, int row0, int col0, int lane){
    int grp = lane >> 3, lr = lane & 7;
    int r = row0 + (grp & 1)*8 + lr;
    int c = col0 + (grp >> 1)*8;
    return arr + (uint32_t)(r*ASTR + c)*2u;
}
__device__ __forceinline__ void stage4(char* sm, uint32_t off_hi, uint32_t off_lo,
                                       int r, int c4, float4 v){
    __nv_bfloat16 h0 = __float2bfloat16_rn(v.x), h1 = __float2bfloat16_rn(v.y),
                  h2 = __float2bfloat16_rn(v.z), h3 = __float2bfloat16_rn(v.w);
    __nv_bfloat16 l0 = __float2bfloat16_rn(v.x - __bfloat162float(h0));
    __nv_bfloat16 l1 = __float2bfloat16_rn(v.y - __bfloat162float(h1));
    __nv_bfloat16 l2 = __float2bfloat16_rn(v.z - __bfloat162float(h2));
    __nv_bfloat16 l3 = __float2bfloat16_rn(v.w - __bfloat162float(h3));
    __nv_bfloat162 hp0, hp1, lp0, lp1;
    hp0.x = h0; hp0.y = h1; hp1.x = h2; hp1.y = h3;
    lp0.x = l0; lp0.y = l1; lp1.x = l2; lp1.y = l3;
    uint32_t byt = (uint32_t)(r*ASTR + c4*4)*2u;
    uint2 uh, ul;
    uh.x = *(uint32_t*)&hp0; uh.y = *(uint32_t*)&hp1;
    ul.x = *(uint32_t*)&lp0; ul.y = *(uint32_t*)&lp1;
    *(uint2*)(sm + off_hi + byt) = uh;
    *(uint2*)(sm + off_lo + byt) = ul;
}

// compute over staged 64x128 A slab vs 128x128 B slab; warp wm in 0..3 (m), nh in 0..1 (n half)
__device__ __forceinline__ void mma_slab64(uint32_t smb, int wm, int n0, int lane,
                                           float (&acc)[8][4]){
#pragma unroll
    for (int kt = 0; kt < 8; ++kt){
        int k0 = kt*16;
        uint32_t ah[4], al[4], bh[8][2], bl[8][2];
        uint32_t adr = frag_addr(smb + AS_HI, wm*16, k0, lane);
        ldsm4(ah, adr);
        ldsm4(al, adr + (AS_LO - AS_HI));
#pragma unroll
        for (int nb = 0; nb < 4; ++nb){
            uint32_t badr = frag_addr(smb + BS_HI2, k0, n0 + nb*16, lane);
            ldsm4t(bh[2*nb][0], bh[2*nb][1], bh[2*nb+1][0], bh[2*nb+1][1], badr);
            ldsm4t(bl[2*nb][0], bl[2*nb][1], bl[2*nb+1][0], bl[2*nb+1][1],
                   badr + (BS_LO2 - BS_HI2));
        }
#pragma unroll
        for (int nt = 0; nt < 8; ++nt){
            mma_bf16(acc[nt], ah, bh[nt][0], bh[nt][1]);
            mma_bf16(acc[nt], ah, bl[nt][0], bl[nt][1]);
            mma_bf16(acc[nt], al, bh[nt][0], bh[nt][1]);
        }
    }
}

// C[M,128] = A[M,128] @ B[128,128]; optional bias; optional fused self-gcn output
__global__ void __launch_bounds__(256) k_gemm_mma(const float* __restrict__ A,
    const float* __restrict__ Bw, float* __restrict__ C, const float* __restrict__ bias,
    float* __restrict__ self_out, const float* __restrict__ bias2,
    const float* __restrict__ dinv, int M)
{
    extern __shared__ char sm[];
    const uint32_t smb = smem_u32(sm);
    const int tid = threadIdx.x, lane = tid & 31, wid = tid >> 5;
    const int wm = wid & 3, n0 = (wid >> 2)*64;
    const int m0 = blockIdx.x * 64;

#pragma unroll
    for (int i = 0; i < 8; ++i){
        int f = tid + i*256, r = f >> 5, c4 = f & 31;
        int row = m0 + r; if (row >= M) row = M - 1;
        stage4(sm, AS_HI, AS_LO, r, c4, *(const float4*)(A + (size_t)row*D + c4*4));
    }
#pragma unroll
    for (int i = 0; i < 16; ++i){
        int f = tid + i*256, r = f >> 5, c4 = f & 31;
        stage4(sm, BS_HI2, BS_LO2, r, c4, *(const float4*)(Bw + (size_t)r*D + c4*4));
    }
    __syncthreads();

    float acc[8][4];
#pragma unroll
    for (int nt = 0; nt < 8; ++nt)
#pragma unroll
        for (int j = 0; j < 4; ++j) acc[nt][j] = 0.f;

    mma_slab64(smb, wm, n0, lane, acc);

#pragma unroll
    for (int nt = 0; nt < 8; ++nt){
        int r = m0 + wm*16 + (lane >> 2);
        int c = n0 + nt*8 + (lane & 3)*2;
        float b0 = bias ? bias[c] : 0.f, b1 = bias ? bias[c+1] : 0.f;
        float d0 = acc[nt][0], d1 = acc[nt][1], d2 = acc[nt][2], d3 = acc[nt][3];
        if (r < M){
            *(float2*)(C + (size_t)r*D + c) = make_float2(d0 + b0, d1 + b1);
            if (self_out){
                float s = dinv[r]; s *= s;
                *(float2*)(self_out + (size_t)r*D + c) =
                    make_float2(bias2[c] + s*d0, bias2[c+1] + s*d1);
            }
        }
        if (r + 8 < M){
            *(float2*)(C + (size_t)(r+8)*D + c) = make_float2(d2 + b0, d3 + b1);
            if (self_out){
                float s = dinv[r+8]; s *= s;
                *(float2*)(self_out + (size_t)(r+8)*D + c) =
                    make_float2(bias2[c] + s*d2, bias2[c+1] + s*d3);
            }
        }
    }
}

// C[t,:] = concat(att[a_t], val[v_t]) @ W (K=256), two staged phases, 64-row tiles
__global__ void __launch_bounds__(256) k_valenc_mma(const int* __restrict__ triples,
    const float* __restrict__ att, const float* __restrict__ val,
    const float* __restrict__ W, float* __restrict__ C, int T)
{
    extern __shared__ char sm[];
    __shared__ int idxA[64], idxV[64];
    const uint32_t smb = smem_u32(sm);
    const int tid = threadIdx.x, lane = tid & 31, wid = tid >> 5;
    const int wm = wid & 3, n0 = (wid >> 2)*64;
    const int m0 = blockIdx.x * 64;
    if (tid < 64){
        int t = m0 + tid; if (t >= T) t = T - 1;
        idxV[tid] = triples[3*t + 1];
        idxA[tid] = triples[3*t + 2];
    }
    __syncthreads();

    float acc[8][4];
#pragma unroll
    for (int nt = 0; nt < 8; ++nt)
#pragma unroll
        for (int j = 0; j < 4; ++j) acc[nt][j] = 0.f;

    for (int ph = 0; ph < 2; ++ph){
        if (ph) __syncthreads();
#pragma unroll
        for (int i = 0; i < 8; ++i){
            int f = tid + i*256, r = f >> 5, c4 = f & 31;
            const float* src = ph ? (val + (size_t)idxV[r]*D) : (att + (size_t)idxA[r]*D);
            stage4(sm, AS_HI, AS_LO, r, c4, *(const float4*)(src + c4*4));
        }
        const float* Wph = W + (size_t)ph*128*D;
#pragma unroll
        for (int i = 0; i < 16; ++i){
            int f = tid + i*256, r = f >> 5, c4 = f & 31;
            stage4(sm, BS_HI2, BS_LO2, r, c4, *(const float4*)(Wph + (size_t)r*D + c4*4));
        }
        __syncthreads();
        mma_slab64(smb, wm, n0, lane, acc);
    }

#pragma unroll
    for (int nt = 0; nt < 8; ++nt){
        int r = m0 + wm*16 + (lane >> 2);
        int c = n0 + nt*8 + (lane & 3)*2;
        if (r < T)
            *(float2*)(C + (size_t)r*D + c) = make_float2(acc[nt][0], acc[nt][1]);
        if (r + 8 < T)
            *(float2*)(C + (size_t)(r+8)*D + c) = make_float2(acc[nt][2], acc[nt][3]);
    }
}

// ---------------- elementwise / edge kernels ----------------
__global__ void k_copy4(const float4* __restrict__ s, float4* __restrict__ d, int n){
    int i = blockIdx.x*blockDim.x + threadIdx.x;
    if (i < n) d[i] = s[i];
}
__global__ void k_seti(int* p, int v, int n){
    int i = blockIdx.x*blockDim.x + threadIdx.x; if (i < n) p[i] = v;
}
__global__ void k_setf(float* p, float v, int n){
    int i = blockIdx.x*blockDim.x + threadIdx.x; if (i < n) p[i] = v;
}
__global__ void k_deg_acc(const int2* __restrict__ ed, int* deg, int E){
    int i = blockIdx.x*blockDim.x + threadIdx.x;
    if (i < E) atomicAdd(deg + ed[i].y, 1);
}
__global__ void k_dinv(const int* __restrict__ deg, float* __restrict__ dinv, int n){
    int i = blockIdx.x*blockDim.x + threadIdx.x;
    if (i < n) dinv[i] = rsqrtf((float)deg[i]);
}
__global__ void k_self_gcn(const float4* __restrict__ h, const float* __restrict__ dinv,
                           const float* __restrict__ b, float4* __restrict__ out, int M){
    int i = blockIdx.x*blockDim.x + threadIdx.x;
    if (i < M*32){
        int j = i >> 5, c = (i & 31)*4;
        float s = dinv[j]; s *= s;
        float4 hv = h[i];
        float4 bv = *(const float4*)(b + c);
        out[i] = make_float4(bv.x + s*hv.x, bv.y + s*hv.y, bv.z + s*hv.z, bv.w + s*hv.w);
    }
}
__global__ void k_gcn_edge(const int2* __restrict__ ed, const float* __restrict__ h,
                           const float* __restrict__ dinv, float* __restrict__ out, int E, int maxd){
    int g = blockIdx.x*blockDim.x + threadIdx.x;
    int lane = g & 31, e = g >> 5;
    if (e >= E) return;
    int2 sd = ed[e];
    if (sd.y >= maxd) return;
    float nrm = dinv[sd.x]*dinv[sd.y];
    float4 hv = *(const float4*)(h + (size_t)sd.x*D + lane*4);
    red4(out + (size_t)sd.y*D + lane*4,
         make_float4(nrm*hv.x, nrm*hv.y, nrm*hv.z, nrm*hv.w));
}
__global__ void k_cnt(const int2* __restrict__ ed, const float* __restrict__ lab,
                      int* cnt, float* ls, int E){
    int i = blockIdx.x*blockDim.x + threadIdx.x;
    if (i < E){ int d = ed[i].y; atomicAdd(cnt + d, 1); atomicAdd(ls + d, lab[i]); }
}
__global__ void k_lattr(const int* __restrict__ cnt, float* __restrict__ ls, int n){
    int i = blockIdx.x*blockDim.x + threadIdx.x;
    if (i < n) ls[i] = ls[i] / fmaxf((float)cnt[i], 1.f);
}
__global__ void k_ce2(const float* __restrict__ We1, const float* __restrict__ ae1,
                      const float* __restrict__ We2, const float* __restrict__ ae2){
    int t = threadIdx.x;
    int lane = t & 31, w = t >> 5;
    const float* We = w ? We2 : We1;
    const float* ae = w ? ae2 : ae1;
    float s = 0.f;
    for (int i = lane; i < D; i += 32) s += We[i]*ae[i];
#pragma unroll
    for (int o = 16; o; o >>= 1) s += __shfl_xor_sync(0xffffffffu, s, o);
    if (lane == 0) g_ce2[w] = s;
}
// warp per row: als/ald both layers; self-exp; z init (max-free softmax)
__global__ void k_att_fused(const float* __restrict__ h1, const float* __restrict__ h2,
    const float* __restrict__ as1, const float* __restrict__ ad1,
    const float* __restrict__ as2, const float* __restrict__ ad2,
    const float* __restrict__ lattr, int M)
{
    int g = blockIdx.x*blockDim.x + threadIdx.x;
    int lane = g & 31, row = g >> 5;
    if (row >= M) return;
    float4 h1v = *(const float4*)(h1 + (size_t)row*D + lane*4);
    float4 h2v = *(const float4*)(h2 + (size_t)row*D + lane*4);
    float4 s1 = *(const float4*)(as1 + lane*4);
    float4 d1 = *(const float4*)(ad1 + lane*4);
    float4 s2 = *(const float4*)(as2 + lane*4);
    float4 d2 = *(const float4*)(ad2 + lane*4);
    float x1 = h1v.x*s1.x + h1v.y*s1.y + h1v.z*s1.z + h1v.w*s1.w;
    float y1 = h1v.x*d1.x + h1v.y*d1.y + h1v.z*d1.z + h1v.w*d1.w;
    float x2 = h2v.x*s2.x + h2v.y*s2.y + h2v.z*s2.z + h2v.w*s2.w;
    float y2 = h2v.x*d2.x + h2v.y*d2.y + h2v.z*d2.z + h2v.w*d2.w;
#pragma unroll
    for (int o = 16; o; o >>= 1){
        x1 += __shfl_xor_sync(0xffffffffu, x1, o);
        y1 += __shfl_xor_sync(0xffffffffu, y1, o);
        x2 += __shfl_xor_sync(0xffffffffu, x2, o);
        y2 += __shfl_xor_sync(0xffffffffu, y2, o);
    }
    if (lane == 0){
        float la = lattr[row];
        g_als2[row] = make_float2(x1, x2);
        g_ald2[row] = make_float2(y1, y2);
        float e1 = __expf(lrelu(x1 + y1 + la*g_ce2[0]));
        float e2 = __expf(lrelu(x2 + y2 + la*g_ce2[1]));
        g_eself2[row] = make_float2(e1, e2);
        g_z2[row] = make_float2(e1, e2);   // z starts with self term
    }
}
// fused: per edge compute exp(alpha) both layers, store, accumulate z
__global__ void k_alpha_z(const int2* __restrict__ ed, const float* __restrict__ lab, int E){
    int i = blockIdx.x*blockDim.x + threadIdx.x;
    if (i >= E) return;
    int2 sd = ed[i];
    float2 als = g_als2[sd.x];
    float2 ald = g_ald2[sd.y];
    float la = lab[i];
    float e1 = __expf(lrelu(als.x + ald.x + la*g_ce2[0]));
    float e2 = __expf(lrelu(als.y + ald.y + la*g_ce2[1]));
    g_exp2[i] = make_float2(e1, e2);
    red2(&g_z2[sd.y].x, make_float2(e1, e2));
}
// out = ent + b1 + b2 + wself1*h1 + wself2*h2
__global__ void k_self2(const float4* __restrict__ ent, const float* __restrict__ b1,
                        const float* __restrict__ b2, const float4* __restrict__ h1,
                        const float4* __restrict__ h2, float4* __restrict__ out, int M){
    int i = blockIdx.x*blockDim.x + threadIdx.x;
    if (i < M*32){
        int j = i >> 5, c = (i & 31)*4;
        float2 es = g_eself2[j]; float2 z = g_z2[j];
        float w1 = es.x / (z.x + 1e-16f);
        float w2 = es.y / (z.y + 1e-16f);
        float4 e = ent[i];
        float4 v1 = *(const float4*)(b1 + c);
        float4 v2 = *(const float4*)(b2 + c);
        float4 x1 = h1[i];
        float4 x2 = h2[i];
        out[i] = make_float4(e.x+v1.x+v2.x + w1*x1.x + w2*x2.x,
                             e.y+v1.y+v2.y + w1*x1.y + w2*x2.y,
                             e.z+v1.z+v2.z + w1*x1.z + w2*x2.z,
                             e.w+v1.w+v2.w + w1*x1.w + w2*x2.w);
    }
}
// warp per edge: out[d] += w1*h1[s] + w2*h2[s]
__global__ void k_gat2_edge(const int2* __restrict__ ed,
                            const float* __restrict__ h1, const float* __restrict__ h2,
                            float* __restrict__ out, int E){
    int g = blockIdx.x*blockDim.x + threadIdx.x;
    int lane = g & 31, e = g >> 5;
    if (e >= E) return;
    int2 sd = ed[e];
    float2 a = g_exp2[e]; float2 z = g_z2[sd.y];
    float w1 = a.x / (z.x + 1e-16f);
    float w2 = a.y / (z.y + 1e-16f);
    float4 x1 = *(const float4*)(h1 + (size_t)sd.x*D + lane*4);
    float4 x2 = *(const float4*)(h2 + (size_t)sd.x*D + lane*4);
    red4(out + (size_t)sd.y*D + lane*4,
         make_float4(w1*x1.x + w2*x2.x, w1*x1.y + w2*x2.y,
                     w1*x1.z + w2*x2.z, w1*x1.w + w2*x2.w));
}

// ---------------- launcher ----------------
extern "C" void kernel_launch(void* const* d_in, const int* in_sizes, int n_in,
                              void* d_out, int out_size)
{
    const int*   triples  = (const int*)  d_in[0];
    const int2*  ent_ed   = (const int2*) d_in[1];
    const float* ent_lab  = (const float*)d_in[2];
    const int2*  val_ed   = (const int2*) d_in[3];
    const float* att      = (const float*)d_in[5];
    const float* valf     = (const float*)d_in[6];
    const float* entf     = (const float*)d_in[7];
    const float* Wp       = (const float*)d_in[8];
    const float* g1W      = (const float*)d_in[9];
    const float* g1b      = (const float*)d_in[10];
    const float* g2W      = (const float*)d_in[11];
    const float* g2b      = (const float*)d_in[12];
    const float* Wl1      = (const float*)d_in[13];
    const float* as1      = (const float*)d_in[14];
    const float* ad1      = (const float*)d_in[15];
    const float* We1      = (const float*)d_in[16];
    const float* ae1      = (const float*)d_in[17];
    const float* gb1      = (const float*)d_in[18];
    const float* Wl2      = (const float*)d_in[19];
    const float* as2      = (const float*)d_in[20];
    const float* ad2      = (const float*)d_in[21];
    const float* We2      = (const float*)d_in[22];
    const float* ae2      = (const float*)d_in[23];
    const float* gb2      = (const float*)d_in[24];

    const int T   = in_sizes[0] / 3;
    const int E1  = in_sizes[1] / 2;
    const int E2  = in_sizes[3] / 2;
    const int NE  = in_sizes[7] / D;
    const int N   = NE + T;
    float* out = (float*)d_out;

    float *nodesA, *nodesB, *hbuf, *dinv, *lattr, *zerov;
    int *deg, *cnt;
    cudaGetSymbolAddress((void**)&nodesA, g_nodesA);
    cudaGetSymbolAddress((void**)&nodesB, g_nodesB);
    cudaGetSymbolAddress((void**)&hbuf,   g_hbuf);
    cudaGetSymbolAddress((void**)&dinv,   g_dinv);
    cudaGetSymbolAddress((void**)&deg,    g_deg);
    cudaGetSymbolAddress((void**)&cnt,    g_cnt);
    cudaGetSymbolAddress((void**)&lattr,  g_lattr);
    cudaGetSymbolAddress((void**)&zerov,  g_zerovec);

    cudaFuncSetAttribute(k_gemm_mma,   cudaFuncAttributeMaxDynamicSharedMemorySize, SMEM_MMA);
    cudaFuncSetAttribute(k_valenc_mma, cudaFuncAttributeMaxDynamicSharedMemorySize, SMEM_MMA);

    const int TB = 256;
    #define GRID1(n) (((n) + TB - 1) / TB)

    // ---- build node features ----
    k_copy4 <<<GRID1(NE*32), TB>>>((const float4*)entf, (float4*)nodesA, NE*32);
    k_valenc_mma<<<(T + 63)/64, TB, SMEM_MMA>>>(triples, att, valf, Wp,
                                                nodesA + (size_t)NE*D, T);
    // ---- degree / norm ----
    k_seti  <<<GRID1(N), TB>>>(deg, 1, N);
    k_deg_acc<<<GRID1(E2), TB>>>(val_ed, deg, E2);
    k_dinv  <<<GRID1(N), TB>>>(deg, dinv, N);

    // ---- GCN layer 1 (transform-first, full N; self-loop fused into epilogue) ----
    k_gemm_mma<<<(N + 63)/64, TB, SMEM_MMA>>>(nodesA, g1W, hbuf,
                                              (const float*)0, nodesB, g1b, dinv, N);
    k_gcn_edge<<<(E2 + 7)/8, TB>>>(val_ed, hbuf, dinv, nodesB, E2, N);

    // ---- GCN layer 2 (aggregate-first: only NE output rows) ----
    k_self_gcn<<<GRID1(NE*32), TB>>>((const float4*)nodesB, dinv, zerov, (float4*)nodesA, NE);
    k_gcn_edge<<<(E2 + 7)/8, TB>>>(val_ed, nodesB, dinv, nodesA, E2, NE);
    k_gemm_mma<<<(NE + 63)/64, TB, SMEM_MMA>>>(nodesA, g2W, hbuf, g2b,
                                               (float*)0, (const float*)0, (const float*)0, NE);

    // ---- GAT prep ----
    k_seti <<<GRID1(NE), TB>>>(cnt, 0, NE);
    k_setf <<<GRID1(NE), TB>>>(lattr, 0.f, NE);
    k_cnt  <<<GRID1(E1), TB>>>(ent_ed, ent_lab, cnt, lattr, E1);
    k_lattr<<<GRID1(NE), TB>>>(cnt, lattr, NE);

    // ---- fused GAT1+GAT2 (max-free softmax) ----
    float* h1 = nodesA;
    float* h2 = nodesB;
    k_gemm_mma<<<(NE + 63)/64, TB, SMEM_MMA>>>(hbuf, Wl1, h1, (const float*)0,
                                               (float*)0, (const float*)0, (const float*)0, NE);
    k_gemm_mma<<<(NE + 63)/64, TB, SMEM_MMA>>>(hbuf, Wl2, h2, (const float*)0,
                                               (float*)0, (const float*)0, (const float*)0, NE);
    k_ce2    <<<1, 64>>>(We1, ae1, We2, ae2);
    k_att_fused<<<(NE + 7)/8, TB>>>(h1, h2, as1, ad1, as2, ad2, lattr, NE);
    k_alpha_z<<<GRID1(E1), TB>>>(ent_ed, ent_lab, E1);
    k_self2  <<<GRID1(NE*32), TB>>>((const float4*)entf, gb1, gb2,
                                    (const float4*)h1, (const float4*)h2, (float4*)out, NE);
    k_gat2_edge<<<(E1 + 7)/8, TB>>>(ent_ed, h1, h2, out, E1);
    #undef GRID1
}

// round 7
// speedup vs baseline: 2.3382x; 1.1368x over previous
#include <cuda_runtime.h>
#include <cuda_bf16.h>
#include <math.h>
#include <stdint.h>

#define D 128
#define MAX_N   400000
#define MAX_E1  1000000
#define MAX_E2  500000
#define MAX_ENT 150000

// ---------------- device scratch ----------------
__device__ float    g_nodesA[(size_t)MAX_N * D];
__device__ float    g_nodesB[(size_t)MAX_N * D];
__device__ float    g_hbuf  [(size_t)MAX_N * D];
__device__ float    g_dinv  [MAX_N];
__device__ int      g_deg   [MAX_N];
__device__ int      g_off   [MAX_N];
__device__ int      g_cur   [MAX_N];
__device__ int      g_bsums [1024];
__device__ int      g_csrc  [MAX_E2];     // val-edge CSR sources
__device__ float2   g_als2  [MAX_ENT];
__device__ float2   g_ald2  [MAX_ENT];
__device__ float2   g_eself2[MAX_ENT];
__device__ int      g_cnt   [MAX_ENT];
__device__ float    g_lattr [MAX_ENT];
__device__ int      g_gsrc  [MAX_E1];     // gat CSR sources
__device__ float2   g_gexp  [MAX_E1];     // gat CSR exp(alpha) payloads
__device__ float    g_ce2[2];
__device__ float    g_zerovec[D];

// ---------------- small helpers ----------------
__device__ __forceinline__ float lrelu(float x){ return x > 0.f ? x : 0.2f * x; }
__device__ __forceinline__ uint32_t smem_u32(const void* p){
    uint32_t a; asm("{ .reg .u64 t; cvta.to.shared.u64 t, %1; cvt.u32.u64 %0, t; }" : "=r"(a) : "l"(p));
    return a;
}
__device__ __forceinline__ float4 f4axpy(float s, float4 a, float4 acc){
    acc.x += s*a.x; acc.y += s*a.y; acc.z += s*a.z; acc.w += s*a.w; return acc;
}

// ---------------- mma.sync bf16x3 GEMM (64-row M tiles) ----------------
#define ASTR   136
#define AS_HI  0u
#define AS_LO  17408u
#define BS_HI2 34816u
#define BS_LO2 69632u
#define SMEM_MMA 104448

__device__ __forceinline__ void ldsm4(uint32_t (&r)[4], uint32_t addr){
    asm volatile("ldmatrix.sync.aligned.m8n8.x4.shared.b16 {%0,%1,%2,%3}, [%4];"
        : "=r"(r[0]), "=r"(r[1]), "=r"(r[2]), "=r"(r[3]) : "r"(addr));
}
__device__ __forceinline__ void ldsm4t(uint32_t &r0, uint32_t &r1, uint32_t &r2, uint32_t &r3, uint32_t addr){
    asm volatile("ldmatrix.sync.aligned.m8n8.x4.trans.shared.b16 {%0,%1,%2,%3}, [%4];"
        : "=r"(r0), "=r"(r1), "=r"(r2), "=r"(r3) : "r"(addr));
}
__device__ __forceinline__ void mma_bf16(float (&d)[4], const uint32_t (&a)[4], uint32_t b0, uint32_t b1){
    asm volatile("mma.sync.aligned.m16n8k16.row.col.f32.bf16.bf16.f32 "
        "{%0,%1,%2,%3}, {%4,%5,%6,%7}, {%8,%9}, {%0,%1,%2,%3};"
        : "+f"(d[0]), "+f"(d[1]), "+f"(d[2]), "+f"(d[3])
        : "r"(a[0]), "r"(a[1]), "r"(a[2]), "r"(a[3]), "r"(b0), "r"(b1));
}
__device__ __forceinline__ uint32_t frag_addr(uint32_t arr, int row0, int col0, int lane){
    int grp = lane >> 3, lr = lane & 7;
    int r = row0 + (grp & 1)*8 + lr;
    int c = col0 + (grp >> 1)*8;
    return arr + (uint32_t)(r*ASTR + c)*2u;
}
__device__ __forceinline__ void stage4(char* sm, uint32_t off_hi, uint32_t off_lo,
                                       int r, int c4, float4 v){
    __nv_bfloat16 h0 = __float2bfloat16_rn(v.x), h1 = __float2bfloat16_rn(v.y),
                  h2 = __float2bfloat16_rn(v.z), h3 = __float2bfloat16_rn(v.w);
    __nv_bfloat16 l0 = __float2bfloat16_rn(v.x - __bfloat162float(h0));
    __nv_bfloat16 l1 = __float2bfloat16_rn(v.y - __bfloat162float(h1));
    __nv_bfloat16 l2 = __float2bfloat16_rn(v.z - __bfloat162float(h2));
    __nv_bfloat16 l3 = __float2bfloat16_rn(v.w - __bfloat162float(h3));
    __nv_bfloat162 hp0, hp1, lp0, lp1;
    hp0.x = h0; hp0.y = h1; hp1.x = h2; hp1.y = h3;
    lp0.x = l0; lp0.y = l1; lp1.x = l2; lp1.y = l3;
    uint32_t byt = (uint32_t)(r*ASTR + c4*4)*2u;
    uint2 uh, ul;
    uh.x = *(uint32_t*)&hp0; uh.y = *(uint32_t*)&hp1;
    ul.x = *(uint32_t*)&lp0; ul.y = *(uint32_t*)&lp1;
    *(uint2*)(sm + off_hi + byt) = uh;
    *(uint2*)(sm + off_lo + byt) = ul;
}

__device__ __forceinline__ void mma_slab64(uint32_t smb, int wm, int n0, int lane,
                                           float (&acc)[8][4]){
#pragma unroll
    for (int kt = 0; kt < 8; ++kt){
        int k0 = kt*16;
        uint32_t ah[4], al[4], bh[8][2], bl[8][2];
        uint32_t adr = frag_addr(smb + AS_HI, wm*16, k0, lane);
        ldsm4(ah, adr);
        ldsm4(al, adr + (AS_LO - AS_HI));
#pragma unroll
        for (int nb = 0; nb < 4; ++nb){
            uint32_t badr = frag_addr(smb + BS_HI2, k0, n0 + nb*16, lane);
            ldsm4t(bh[2*nb][0], bh[2*nb][1], bh[2*nb+1][0], bh[2*nb+1][1], badr);
            ldsm4t(bl[2*nb][0], bl[2*nb][1], bl[2*nb+1][0], bl[2*nb+1][1],
                   badr + (BS_LO2 - BS_HI2));
        }
#pragma unroll
        for (int nt = 0; nt < 8; ++nt){
            mma_bf16(acc[nt], ah, bh[nt][0], bh[nt][1]);
            mma_bf16(acc[nt], ah, bl[nt][0], bl[nt][1]);
            mma_bf16(acc[nt], al, bh[nt][0], bh[nt][1]);
        }
    }
}

// C[r, c] at row stride ldc; C = A[M,128] @ B[128,128] (+bias)
__global__ void __launch_bounds__(256) k_gemm_mma(const float* __restrict__ A,
    const float* __restrict__ Bw, float* __restrict__ C, const float* __restrict__ bias,
    int ldc, int M)
{
    extern __shared__ char sm[];
    const uint32_t smb = smem_u32(sm);
    const int tid = threadIdx.x, lane = tid & 31, wid = tid >> 5;
    const int wm = wid & 3, n0 = (wid >> 2)*64;
    const int m0 = blockIdx.x * 64;

#pragma unroll
    for (int i = 0; i < 8; ++i){
        int f = tid + i*256, r = f >> 5, c4 = f & 31;
        int row = m0 + r; if (row >= M) row = M - 1;
        stage4(sm, AS_HI, AS_LO, r, c4, *(const float4*)(A + (size_t)row*D + c4*4));
    }
#pragma unroll
    for (int i = 0; i < 16; ++i){
        int f = tid + i*256, r = f >> 5, c4 = f & 31;
        stage4(sm, BS_HI2, BS_LO2, r, c4, *(const float4*)(Bw + (size_t)r*D + c4*4));
    }
    __syncthreads();

    float acc[8][4];
#pragma unroll
    for (int nt = 0; nt < 8; ++nt)
#pragma unroll
        for (int j = 0; j < 4; ++j) acc[nt][j] = 0.f;

    mma_slab64(smb, wm, n0, lane, acc);

#pragma unroll
    for (int nt = 0; nt < 8; ++nt){
        int r = m0 + wm*16 + (lane >> 2);
        int c = n0 + nt*8 + (lane & 3)*2;
        float b0 = bias ? bias[c] : 0.f, b1 = bias ? bias[c+1] : 0.f;
        if (r < M)
            *(float2*)(C + (size_t)r*ldc + c) = make_float2(acc[nt][0] + b0, acc[nt][1] + b1);
        if (r + 8 < M)
            *(float2*)(C + (size_t)(r+8)*ldc + c) = make_float2(acc[nt][2] + b0, acc[nt][3] + b1);
    }
}

// C[t,:] = concat(att[a_t], val[v_t]) @ W (K=256)
__global__ void __launch_bounds__(256) k_valenc_mma(const int* __restrict__ triples,
    const float* __restrict__ att, const float* __restrict__ val,
    const float* __restrict__ W, float* __restrict__ C, int T)
{
    extern __shared__ char sm[];
    __shared__ int idxA[64], idxV[64];
    const uint32_t smb = smem_u32(sm);
    const int tid = threadIdx.x, lane = tid & 31, wid = tid >> 5;
    const int wm = wid & 3, n0 = (wid >> 2)*64;
    const int m0 = blockIdx.x * 64;
    if (tid < 64){
        int t = m0 + tid; if (t >= T) t = T - 1;
        idxV[tid] = triples[3*t + 1];
        idxA[tid] = triples[3*t + 2];
    }
    __syncthreads();

    float acc[8][4];
#pragma unroll
    for (int nt = 0; nt < 8; ++nt)
#pragma unroll
        for (int j = 0; j < 4; ++j) acc[nt][j] = 0.f;

    for (int ph = 0; ph < 2; ++ph){
        if (ph) __syncthreads();
#pragma unroll
        for (int i = 0; i < 8; ++i){
            int f = tid + i*256, r = f >> 5, c4 = f & 31;
            const float* src = ph ? (val + (size_t)idxV[r]*D) : (att + (size_t)idxA[r]*D);
            stage4(sm, AS_HI, AS_LO, r, c4, *(const float4*)(src + c4*4));
        }
        const float* Wph = W + (size_t)ph*128*D;
#pragma unroll
        for (int i = 0; i < 16; ++i){
            int f = tid + i*256, r = f >> 5, c4 = f & 31;
            stage4(sm, BS_HI2, BS_LO2, r, c4, *(const float4*)(Wph + (size_t)r*D + c4*4));
        }
        __syncthreads();
        mma_slab64(smb, wm, n0, lane, acc);
    }

#pragma unroll
    for (int nt = 0; nt < 8; ++nt){
        int r = m0 + wm*16 + (lane >> 2);
        int c = n0 + nt*8 + (lane & 3)*2;
        if (r < T)
            *(float2*)(C + (size_t)r*D + c) = make_float2(acc[nt][0], acc[nt][1]);
        if (r + 8 < T)
            *(float2*)(C + (size_t)(r+8)*D + c) = make_float2(acc[nt][2], acc[nt][3]);
    }
}

// ---------------- scan (exclusive, 3-kernel) ----------------
#define SCAN_B 1024
__global__ void k_scan1(const int* __restrict__ in, int* __restrict__ out,
                        int* __restrict__ bsums, int n){
    __shared__ int s[SCAN_B];
    int t = threadIdx.x, idx = blockIdx.x*SCAN_B + t;
    int v = (idx < n) ? in[idx] : 0;
    s[t] = v; __syncthreads();
    for (int o = 1; o < SCAN_B; o <<= 1){
        int x = (t >= o) ? s[t-o] : 0; __syncthreads();
        s[t] += x; __syncthreads();
    }
    if (idx < n) out[idx] = s[t] - v;
    if (t == SCAN_B-1) bsums[blockIdx.x] = s[t];
}
__global__ void k_scan2(int* __restrict__ bsums, int nb){
    __shared__ int s[SCAN_B];
    int t = threadIdx.x;
    int v = (t < nb) ? bsums[t] : 0;
    s[t] = v; __syncthreads();
    for (int o = 1; o < SCAN_B; o <<= 1){
        int x = (t >= o) ? s[t-o] : 0; __syncthreads();
        s[t] += x; __syncthreads();
    }
    if (t < nb) bsums[t] = s[t] - v;
}
__global__ void k_scan3(int* __restrict__ out, const int* __restrict__ bsums, int n){
    int idx = blockIdx.x*blockDim.x + threadIdx.x;
    if (idx < n) out[idx] += bsums[idx >> 10];
}

// ---------------- elementwise / build kernels ----------------
__global__ void k_copy4(const float4* __restrict__ s, float4* __restrict__ d, int n){
    int i = blockIdx.x*blockDim.x + threadIdx.x;
    if (i < n) d[i] = s[i];
}
__global__ void k_copyi(const int* __restrict__ s, int* __restrict__ d, int n){
    int i = blockIdx.x*blockDim.x + threadIdx.x;
    if (i < n) d[i] = s[i];
}
__global__ void k_seti(int* p, int v, int n){
    int i = blockIdx.x*blockDim.x + threadIdx.x; if (i < n) p[i] = v;
}
__global__ void k_setf(float* p, float v, int n){
    int i = blockIdx.x*blockDim.x + threadIdx.x; if (i < n) p[i] = v;
}
__global__ void k_deg_acc(const int2* __restrict__ ed, int* deg, int E){
    int i = blockIdx.x*blockDim.x + threadIdx.x;
    if (i < E) atomicAdd(deg + ed[i].y, 1);
}
__global__ void k_dinv(const int* __restrict__ deg, float* __restrict__ dinv, int n){
    int i = blockIdx.x*blockDim.x + threadIdx.x;
    if (i < n) dinv[i] = rsqrtf((float)(deg[i] + 1));
}
__global__ void k_scat_val(const int2* __restrict__ ed, int* cur, int* csrc, int E){
    int i = blockIdx.x*blockDim.x + threadIdx.x;
    if (i >= E) return;
    int2 sd = ed[i];
    int pos = atomicAdd(cur + sd.y, 1);
    csrc[pos] = sd.x;
}
// warp per dst: out[d] = b + dinv[d]^2 h[d] + sum dinv[s]dinv[d] h[s]
__global__ void k_gcn_csr(const float* __restrict__ h, const float* __restrict__ dinv,
                          const float* __restrict__ b, float* __restrict__ out,
                          const int* __restrict__ off, const int* __restrict__ deg,
                          const int* __restrict__ csrc, int M)
{
    int g = blockIdx.x*blockDim.x + threadIdx.x;
    int lane = g & 31, d = g >> 5;
    if (d >= M) return;
    float did = dinv[d];
    float4 hv = ((const float4*)(h + (size_t)d*D))[lane];
    float4 acc = *(const float4*)(b + lane*4);
    acc = f4axpy(did*did, hv, acc);
    int e0 = off[d], n = deg[d];
    for (int e = e0; e < e0 + n; ++e){
        int s = csrc[e];
        float nrm = dinv[s]*did;
        float4 xv = ((const float4*)(h + (size_t)s*D))[lane];
        acc = f4axpy(nrm, xv, acc);
    }
    ((float4*)(out + (size_t)d*D))[lane] = acc;
}
__global__ void k_cnt(const int2* __restrict__ ed, const float* __restrict__ lab,
                      int* cnt, float* ls, int E){
    int i = blockIdx.x*blockDim.x + threadIdx.x;
    if (i < E){ int d = ed[i].y; atomicAdd(cnt + d, 1); atomicAdd(ls + d, lab[i]); }
}
__global__ void k_lattr(const int* __restrict__ cnt, float* __restrict__ ls, int n){
    int i = blockIdx.x*blockDim.x + threadIdx.x;
    if (i < n) ls[i] = ls[i] / fmaxf((float)cnt[i], 1.f);
}
__global__ void k_ce2(const float* __restrict__ We1, const float* __restrict__ ae1,
                      const float* __restrict__ We2, const float* __restrict__ ae2){
    int t = threadIdx.x;
    int lane = t & 31, w = t >> 5;
    const float* We = w ? We2 : We1;
    const float* ae = w ? ae2 : ae1;
    float s = 0.f;
    for (int i = lane; i < D; i += 32) s += We[i]*ae[i];
#pragma unroll
    for (int o = 16; o; o >>= 1) s += __shfl_xor_sync(0xffffffffu, s, o);
    if (lane == 0) g_ce2[w] = s;
}
// warp per row over interleaved hcat (stride 256: h1 at +0, h2 at +128)
__global__ void k_att_fused(const float* __restrict__ hcat,
    const float* __restrict__ as1, const float* __restrict__ ad1,
    const float* __restrict__ as2, const float* __restrict__ ad2,
    const float* __restrict__ lattr, int M)
{
    int g = blockIdx.x*blockDim.x + threadIdx.x;
    int lane = g & 31, row = g >> 5;
    if (row >= M) return;
    const float4* hp = (const float4*)(hcat + (size_t)row*256);
    float4 h1v = hp[lane];
    float4 h2v = hp[lane + 32];
    float4 s1 = *(const float4*)(as1 + lane*4);
    float4 d1 = *(const float4*)(ad1 + lane*4);
    float4 s2 = *(const float4*)(as2 + lane*4);
    float4 d2 = *(const float4*)(ad2 + lane*4);
    float x1 = h1v.x*s1.x + h1v.y*s1.y + h1v.z*s1.z + h1v.w*s1.w;
    float y1 = h1v.x*d1.x + h1v.y*d1.y + h1v.z*d1.z + h1v.w*d1.w;
    float x2 = h2v.x*s2.x + h2v.y*s2.y + h2v.z*s2.z + h2v.w*s2.w;
    float y2 = h2v.x*d2.x + h2v.y*d2.y + h2v.z*d2.z + h2v.w*d2.w;
#pragma unroll
    for (int o = 16; o; o >>= 1){
        x1 += __shfl_xor_sync(0xffffffffu, x1, o);
        y1 += __shfl_xor_sync(0xffffffffu, y1, o);
        x2 += __shfl_xor_sync(0xffffffffu, x2, o);
        y2 += __shfl_xor_sync(0xffffffffu, y2, o);
    }
    if (lane == 0){
        float la = lattr[row];
        g_als2[row] = make_float2(x1, x2);
        g_ald2[row] = make_float2(y1, y2);
        float e1 = __expf(lrelu(x1 + y1 + la*g_ce2[0]));
        float e2 = __expf(lrelu(x2 + y2 + la*g_ce2[1]));
        g_eself2[row] = make_float2(e1, e2);
    }
}
// per edge: exp(alpha) both layers, scatter into CSR slot
__global__ void k_alpha_scat(const int2* __restrict__ ed, const float* __restrict__ lab,
                             int* cur, int E){
    int i = blockIdx.x*blockDim.x + threadIdx.x;
    if (i >= E) return;
    int2 sd = ed[i];
    float2 als = g_als2[sd.x];
    float2 ald = g_ald2[sd.y];
    float la = lab[i];
    float e1 = __expf(lrelu(als.x + ald.x + la*g_ce2[0]));
    float e2 = __expf(lrelu(als.y + ald.y + la*g_ce2[1]));
    int pos = atomicAdd(cur + sd.y, 1);
    g_gsrc[pos] = sd.x;
    g_gexp[pos] = make_float2(e1, e2);
}
// warp per dst: full fused GAT output (both layers + softmax + self + bias + residual)
__global__ void k_gat_csr(const float* __restrict__ hcat, const float4* __restrict__ ent,
                          const float* __restrict__ b1, const float* __restrict__ b2,
                          const int* __restrict__ off, const int* __restrict__ cnt,
                          float* __restrict__ out, int M)
{
    int g = blockIdx.x*blockDim.x + threadIdx.x;
    int lane = g & 31, d = g >> 5;
    if (d >= M) return;
    float2 es = g_eself2[d];
    const float4* hp = (const float4*)(hcat + (size_t)d*256);
    float4 h1v = hp[lane], h2v = hp[lane + 32];
    float z1 = es.x, z2 = es.y;
    float4 a1 = make_float4(es.x*h1v.x, es.x*h1v.y, es.x*h1v.z, es.x*h1v.w);
    float4 a2 = make_float4(es.y*h2v.x, es.y*h2v.y, es.y*h2v.z, es.y*h2v.w);
    int e0 = off[d], n = cnt[d];
    for (int e = e0; e < e0 + n; ++e){
        int s = g_gsrc[e];
        float2 ee = g_gexp[e];
        const float4* sp = (const float4*)(hcat + (size_t)s*256);
        a1 = f4axpy(ee.x, sp[lane], a1);
        a2 = f4axpy(ee.y, sp[lane + 32], a2);
        z1 += ee.x; z2 += ee.y;
    }
    float i1 = 1.f/(z1 + 1e-16f), i2 = 1.f/(z2 + 1e-16f);
    float4 ev = ent[(size_t)d*32 + lane];
    float4 bv1 = *(const float4*)(b1 + lane*4);
    float4 bv2 = *(const float4*)(b2 + lane*4);
    float4 o;
    o.x = ev.x + bv1.x + bv2.x + i1*a1.x + i2*a2.x;
    o.y = ev.y + bv1.y + bv2.y + i1*a1.y + i2*a2.y;
    o.z = ev.z + bv1.z + bv2.z + i1*a1.z + i2*a2.z;
    o.w = ev.w + bv1.w + bv2.w + i1*a1.w + i2*a2.w;
    ((float4*)(out + (size_t)d*D))[lane] = o;
}

// ---------------- launcher ----------------
extern "C" void kernel_launch(void* const* d_in, const int* in_sizes, int n_in,
                              void* d_out, int out_size)
{
    const int*   triples  = (const int*)  d_in[0];
    const int2*  ent_ed   = (const int2*) d_in[1];
    const float* ent_lab  = (const float*)d_in[2];
    const int2*  val_ed   = (const int2*) d_in[3];
    const float* att      = (const float*)d_in[5];
    const float* valf     = (const float*)d_in[6];
    const float* entf     = (const float*)d_in[7];
    const float* Wp       = (const float*)d_in[8];
    const float* g1W      = (const float*)d_in[9];
    const float* g1b      = (const float*)d_in[10];
    const float* g2W      = (const float*)d_in[11];
    const float* g2b      = (const float*)d_in[12];
    const float* Wl1      = (const float*)d_in[13];
    const float* as1      = (const float*)d_in[14];
    const float* ad1      = (const float*)d_in[15];
    const float* We1      = (const float*)d_in[16];
    const float* ae1      = (const float*)d_in[17];
    const float* gb1      = (const float*)d_in[18];
    const float* Wl2      = (const float*)d_in[19];
    const float* as2      = (const float*)d_in[20];
    const float* ad2      = (const float*)d_in[21];
    const float* We2      = (const float*)d_in[22];
    const float* ae2      = (const float*)d_in[23];
    const float* gb2      = (const float*)d_in[24];

    const int T   = in_sizes[0] / 3;
    const int E1  = in_sizes[1] / 2;
    const int E2  = in_sizes[3] / 2;
    const int NE  = in_sizes[7] / D;
    const int N   = NE + T;
    float* out = (float*)d_out;

    float *nodesA, *nodesB, *hbuf, *dinv, *lattr, *zerov;
    int *deg, *cnt, *off, *cur, *bsums, *csrc;
    cudaGetSymbolAddress((void**)&nodesA, g_nodesA);
    cudaGetSymbolAddress((void**)&nodesB, g_nodesB);
    cudaGetSymbolAddress((void**)&hbuf,   g_hbuf);
    cudaGetSymbolAddress((void**)&dinv,   g_dinv);
    cudaGetSymbolAddress((void**)&deg,    g_deg);
    cudaGetSymbolAddress((void**)&cnt,    g_cnt);
    cudaGetSymbolAddress((void**)&lattr,  g_lattr);
    cudaGetSymbolAddress((void**)&zerov,  g_zerovec);
    cudaGetSymbolAddress((void**)&off,    g_off);
    cudaGetSymbolAddress((void**)&cur,    g_cur);
    cudaGetSymbolAddress((void**)&bsums,  g_bsums);
    cudaGetSymbolAddress((void**)&csrc,   g_csrc);

    cudaFuncSetAttribute(k_gemm_mma,   cudaFuncAttributeMaxDynamicSharedMemorySize, SMEM_MMA);
    cudaFuncSetAttribute(k_valenc_mma, cudaFuncAttributeMaxDynamicSharedMemorySize, SMEM_MMA);

    const int TB = 256;
    #define GRID1(n) (((n) + TB - 1) / TB)

    // ---- build node features ----
    k_copy4 <<<GRID1(NE*32), TB>>>((const float4*)entf, (float4*)nodesA, NE*32);
    k_valenc_mma<<<(T + 63)/64, TB, SMEM_MMA>>>(triples, att, valf, Wp,
                                                nodesA + (size_t)NE*D, T);

    // ---- val-edge CSR + dinv ----
    k_seti   <<<GRID1(N), TB>>>(deg, 0, N);
    k_deg_acc<<<GRID1(E2), TB>>>(val_ed, deg, E2);
    k_dinv   <<<GRID1(N), TB>>>(deg, dinv, N);
    {
        int nb = (N + SCAN_B - 1)/SCAN_B;
        k_scan1<<<nb, SCAN_B>>>(deg, off, bsums, N);
        k_scan2<<<1, SCAN_B>>>(bsums, nb);
        k_scan3<<<GRID1(N), TB>>>(off, bsums, N);
    }
    k_copyi   <<<GRID1(N), TB>>>(off, cur, N);
    k_scat_val<<<GRID1(E2), TB>>>(val_ed, cur, csrc, E2);

    // ---- GCN layer 1 (transform then CSR-aggregate, full N) ----
    k_gemm_mma<<<(N + 63)/64, TB, SMEM_MMA>>>(nodesA, g1W, hbuf, (const float*)0, D, N);
    k_gcn_csr<<<GRID1(N*32), TB>>>(hbuf, dinv, g1b, nodesB, off, deg, csrc, N);

    // ---- GCN layer 2 (aggregate-first, NE rows; then transform) ----
    k_gcn_csr<<<GRID1(NE*32), TB>>>(nodesB, dinv, zerov, nodesA, off, deg, csrc, NE);
    k_gemm_mma<<<(NE + 63)/64, TB, SMEM_MMA>>>(nodesA, g2W, hbuf, g2b, D, NE);

    // ---- GAT prep: lattr + ent-edge CSR offsets ----
    k_seti <<<GRID1(NE), TB>>>(cnt, 0, NE);
    k_setf <<<GRID1(NE), TB>>>(lattr, 0.f, NE);
    k_cnt  <<<GRID1(E1), TB>>>(ent_ed, ent_lab, cnt, lattr, E1);
    k_lattr<<<GRID1(NE), TB>>>(cnt, lattr, NE);
    {
        int nb = (NE + SCAN_B - 1)/SCAN_B;
        k_scan1<<<nb, SCAN_B>>>(cnt, off, bsums, NE);
        k_scan2<<<1, SCAN_B>>>(bsums, nb);
        k_scan3<<<GRID1(NE), TB>>>(off, bsums, NE);
    }
    k_copyi<<<GRID1(NE), TB>>>(off, cur, NE);

    // ---- GAT GEMMs into interleaved hcat (row stride 256) ----
    float* hcat = nodesA;
    k_gemm_mma<<<(NE + 63)/64, TB, SMEM_MMA>>>(hbuf, Wl1, hcat,       (const float*)0, 256, NE);
    k_gemm_mma<<<(NE + 63)/64, TB, SMEM_MMA>>>(hbuf, Wl2, hcat + 128, (const float*)0, 256, NE);

    // ---- fused GAT1+GAT2 ----
    k_ce2       <<<1, 64>>>(We1, ae1, We2, ae2);
    k_att_fused <<<(NE + 7)/8, TB>>>(hcat, as1, ad1, as2, ad2, lattr, NE);
    k_alpha_scat<<<GRID1(E1), TB>>>(ent_ed, ent_lab, cur, E1);
    k_gat_csr   <<<GRID1(NE*32), TB>>>(hcat, (const float4*)entf, gb1, gb2,
                                       off, cnt, out, NE);
    #undef GRID1
}

// round 8
// speedup vs baseline: 2.4854x; 1.0629x over previous
#include <cuda_runtime.h>
#include <cuda_bf16.h>
#include <math.h>
#include <stdint.h>

#define D 128
#define MAX_N   400000
#define MAX_E1  1000000
#define MAX_E2  500000
#define MAX_ENT 150000

// ---------------- device scratch ----------------
__device__ float    g_nodesA[(size_t)MAX_N * D];
__device__ float    g_nodesB[(size_t)MAX_N * D];
__device__ float    g_hbuf  [(size_t)MAX_N * D];
__device__ float    g_dinv  [MAX_N];
__device__ int      g_deg   [MAX_N];
__device__ int      g_off   [MAX_N];
__device__ int      g_cur   [MAX_N];
__device__ int      g_bsums [1024];
__device__ int      g_csrc  [MAX_E2];
__device__ int      g_offE  [MAX_ENT];
__device__ int      g_curE  [MAX_ENT];
__device__ int      g_bsumsE[1024];
__device__ float2   g_als2  [MAX_ENT];
__device__ float2   g_ald2  [MAX_ENT];
__device__ float2   g_eself2[MAX_ENT];
__device__ int      g_cnt   [MAX_ENT];
__device__ float    g_lattr [MAX_ENT];
__device__ int      g_gsrc  [MAX_E1];
__device__ float2   g_gexp  [MAX_E1];
__device__ float    g_ce2[2];
__device__ float    g_zerovec[D];

// ---------------- small helpers ----------------
__device__ __forceinline__ float lrelu(float x){ return x > 0.f ? x : 0.2f * x; }
__device__ __forceinline__ uint32_t smem_u32(const void* p){
    uint32_t a; asm("{ .reg .u64 t; cvta.to.shared.u64 t, %1; cvt.u32.u64 %0, t; }" : "=r"(a) : "l"(p));
    return a;
}
__device__ __forceinline__ float4 f4axpy(float s, float4 a, float4 acc){
    acc.x += s*a.x; acc.y += s*a.y; acc.z += s*a.z; acc.w += s*a.w; return acc;
}

// ---------------- mma.sync bf16x3 GEMM (64-row M tiles) ----------------
#define ASTR   136
#define AS_HI  0u
#define AS_LO  17408u
#define BS_HI2 34816u
#define BS_LO2 69632u
#define SMEM_MMA 104448

__device__ __forceinline__ void ldsm4(uint32_t (&r)[4], uint32_t addr){
    asm volatile("ldmatrix.sync.aligned.m8n8.x4.shared.b16 {%0,%1,%2,%3}, [%4];"
        : "=r"(r[0]), "=r"(r[1]), "=r"(r[2]), "=r"(r[3]) : "r"(addr));
}
__device__ __forceinline__ void ldsm4t(uint32_t &r0, uint32_t &r1, uint32_t &r2, uint32_t &r3, uint32_t addr){
    asm volatile("ldmatrix.sync.aligned.m8n8.x4.trans.shared.b16 {%0,%1,%2,%3}, [%4];"
        : "=r"(r0), "=r"(r1), "=r"(r2), "=r"(r3) : "r"(addr));
}
__device__ __forceinline__ void mma_bf16(float (&d)[4], const uint32_t (&a)[4], uint32_t b0, uint32_t b1){
    asm volatile("mma.sync.aligned.m16n8k16.row.col.f32.bf16.bf16.f32 "
        "{%0,%1,%2,%3}, {%4,%5,%6,%7}, {%8,%9}, {%0,%1,%2,%3};"
        : "+f"(d[0]), "+f"(d[1]), "+f"(d[2]), "+f"(d[3])
        : "r"(a[0]), "r"(a[1]), "r"(a[2]), "r"(a[3]), "r"(b0), "r"(b1));
}
__device__ __forceinline__ uint32_t frag_addr(uint32_t arr, int row0, int col0, int lane){
    int grp = lane >> 3, lr = lane & 7;
    int r = row0 + (grp & 1)*8 + lr;
    int c = col0 + (grp >> 1)*8;
    return arr + (uint32_t)(r*ASTR + c)*2u;
}
__device__ __forceinline__ void stage4(char* sm, uint32_t off_hi, uint32_t off_lo,
                                       int r, int c4, float4 v){
    __nv_bfloat16 h0 = __float2bfloat16_rn(v.x), h1 = __float2bfloat16_rn(v.y),
                  h2 = __float2bfloat16_rn(v.z), h3 = __float2bfloat16_rn(v.w);
    __nv_bfloat16 l0 = __float2bfloat16_rn(v.x - __bfloat162float(h0));
    __nv_bfloat16 l1 = __float2bfloat16_rn(v.y - __bfloat162float(h1));
    __nv_bfloat16 l2 = __float2bfloat16_rn(v.z - __bfloat162float(h2));
    __nv_bfloat16 l3 = __float2bfloat16_rn(v.w - __bfloat162float(h3));
    __nv_bfloat162 hp0, hp1, lp0, lp1;
    hp0.x = h0; hp0.y = h1; hp1.x = h2; hp1.y = h3;
    lp0.x = l0; lp0.y = l1; lp1.x = l2; lp1.y = l3;
    uint32_t byt = (uint32_t)(r*ASTR + c4*4)*2u;
    uint2 uh, ul;
    uh.x = *(uint32_t*)&hp0; uh.y = *(uint32_t*)&hp1;
    ul.x = *(uint32_t*)&lp0; ul.y = *(uint32_t*)&lp1;
    *(uint2*)(sm + off_hi + byt) = uh;
    *(uint2*)(sm + off_lo + byt) = ul;
}

__device__ __forceinline__ void mma_slab64(uint32_t smb, int wm, int n0, int lane,
                                           float (&acc)[8][4]){
#pragma unroll
    for (int kt = 0; kt < 8; ++kt){
        int k0 = kt*16;
        uint32_t ah[4], al[4], bh[8][2], bl[8][2];
        uint32_t adr = frag_addr(smb + AS_HI, wm*16, k0, lane);
        ldsm4(ah, adr);
        ldsm4(al, adr + (AS_LO - AS_HI));
#pragma unroll
        for (int nb = 0; nb < 4; ++nb){
            uint32_t badr = frag_addr(smb + BS_HI2, k0, n0 + nb*16, lane);
            ldsm4t(bh[2*nb][0], bh[2*nb][1], bh[2*nb+1][0], bh[2*nb+1][1], badr);
            ldsm4t(bl[2*nb][0], bl[2*nb][1], bl[2*nb+1][0], bl[2*nb+1][1],
                   badr + (BS_LO2 - BS_HI2));
        }
#pragma unroll
        for (int nt = 0; nt < 8; ++nt){
            mma_bf16(acc[nt], ah, bh[nt][0], bh[nt][1]);
            mma_bf16(acc[nt], ah, bl[nt][0], bl[nt][1]);
            mma_bf16(acc[nt], al, bh[nt][0], bh[nt][1]);
        }
    }
}

// C = A @ B (+bias). A rows < split come from Alow, rows >= split from Ahigh (base row = split).
__global__ void __launch_bounds__(256) k_gemm_mma(const float* __restrict__ Alow,
    const float* __restrict__ Ahigh, int split,
    const float* __restrict__ Bw, float* __restrict__ C, const float* __restrict__ bias,
    int ldc, int M)
{
    extern __shared__ char sm[];
    const uint32_t smb = smem_u32(sm);
    const int tid = threadIdx.x, lane = tid & 31, wid = tid >> 5;
    const int wm = wid & 3, n0 = (wid >> 2)*64;
    const int m0 = blockIdx.x * 64;

#pragma unroll
    for (int i = 0; i < 8; ++i){
        int f = tid + i*256, r = f >> 5, c4 = f & 31;
        int row = m0 + r; if (row >= M) row = M - 1;
        const float* src = (row < split) ? (Alow + (size_t)row*D)
                                         : (Ahigh + (size_t)(row - split)*D);
        stage4(sm, AS_HI, AS_LO, r, c4, *(const float4*)(src + c4*4));
    }
#pragma unroll
    for (int i = 0; i < 16; ++i){
        int f = tid + i*256, r = f >> 5, c4 = f & 31;
        stage4(sm, BS_HI2, BS_LO2, r, c4, *(const float4*)(Bw + (size_t)r*D + c4*4));
    }
    __syncthreads();

    float acc[8][4];
#pragma unroll
    for (int nt = 0; nt < 8; ++nt)
#pragma unroll
        for (int j = 0; j < 4; ++j) acc[nt][j] = 0.f;

    mma_slab64(smb, wm, n0, lane, acc);

#pragma unroll
    for (int nt = 0; nt < 8; ++nt){
        int r = m0 + wm*16 + (lane >> 2);
        int c = n0 + nt*8 + (lane & 3)*2;
        float b0 = bias ? bias[c] : 0.f, b1 = bias ? bias[c+1] : 0.f;
        if (r < M)
            *(float2*)(C + (size_t)r*ldc + c) = make_float2(acc[nt][0] + b0, acc[nt][1] + b1);
        if (r + 8 < M)
            *(float2*)(C + (size_t)(r+8)*ldc + c) = make_float2(acc[nt][2] + b0, acc[nt][3] + b1);
    }
}

// C[t,:] = concat(att[a_t], val[v_t]) @ W (K=256)
__global__ void __launch_bounds__(256) k_valenc_mma(const int* __restrict__ triples,
    const float* __restrict__ att, const float* __restrict__ val,
    const float* __restrict__ W, float* __restrict__ C, int T)
{
    extern __shared__ char sm[];
    __shared__ int idxA[64], idxV[64];
    const uint32_t smb = smem_u32(sm);
    const int tid = threadIdx.x, lane = tid & 31, wid = tid >> 5;
    const int wm = wid & 3, n0 = (wid >> 2)*64;
    const int m0 = blockIdx.x * 64;
    if (tid < 64){
        int t = m0 + tid; if (t >= T) t = T - 1;
        idxV[tid] = triples[3*t + 1];
        idxA[tid] = triples[3*t + 2];
    }
    __syncthreads();

    float acc[8][4];
#pragma unroll
    for (int nt = 0; nt < 8; ++nt)
#pragma unroll
        for (int j = 0; j < 4; ++j) acc[nt][j] = 0.f;

    for (int ph = 0; ph < 2; ++ph){
        if (ph) __syncthreads();
#pragma unroll
        for (int i = 0; i < 8; ++i){
            int f = tid + i*256, r = f >> 5, c4 = f & 31;
            const float* src = ph ? (val + (size_t)idxV[r]*D) : (att + (size_t)idxA[r]*D);
            stage4(sm, AS_HI, AS_LO, r, c4, *(const float4*)(src + c4*4));
        }
        const float* Wph = W + (size_t)ph*128*D;
#pragma unroll
        for (int i = 0; i < 16; ++i){
            int f = tid + i*256, r = f >> 5, c4 = f & 31;
            stage4(sm, BS_HI2, BS_LO2, r, c4, *(const float4*)(Wph + (size_t)r*D + c4*4));
        }
        __syncthreads();
        mma_slab64(smb, wm, n0, lane, acc);
    }

#pragma unroll
    for (int nt = 0; nt < 8; ++nt){
        int r = m0 + wm*16 + (lane >> 2);
        int c = n0 + nt*8 + (lane & 3)*2;
        if (r < T)
            *(float2*)(C + (size_t)r*D + c) = make_float2(acc[nt][0], acc[nt][1]);
        if (r + 8 < T)
            *(float2*)(C + (size_t)(r+8)*D + c) = make_float2(acc[nt][2], acc[nt][3]);
    }
}

// ---------------- scan (exclusive, 3-kernel) ----------------
#define SCAN_B 1024
__global__ void k_scan1(const int* __restrict__ in, int* __restrict__ out,
                        int* __restrict__ bsums, int n){
    __shared__ int s[SCAN_B];
    int t = threadIdx.x, idx = blockIdx.x*SCAN_B + t;
    int v = (idx < n) ? in[idx] : 0;
    s[t] = v; __syncthreads();
    for (int o = 1; o < SCAN_B; o <<= 1){
        int x = (t >= o) ? s[t-o] : 0; __syncthreads();
        s[t] += x; __syncthreads();
    }
    if (idx < n) out[idx] = s[t] - v;
    if (t == SCAN_B-1) bsums[blockIdx.x] = s[t];
}
__global__ void k_scan2(int* __restrict__ bsums, int nb){
    __shared__ int s[SCAN_B];
    int t = threadIdx.x;
    int v = (t < nb) ? bsums[t] : 0;
    s[t] = v; __syncthreads();
    for (int o = 1; o < SCAN_B; o <<= 1){
        int x = (t >= o) ? s[t-o] : 0; __syncthreads();
        s[t] += x; __syncthreads();
    }
    if (t < nb) bsums[t] = s[t] - v;
}
// val-branch fixup: off += bsums; cur = off; dinv = rsqrt(deg+1)
__global__ void k_scan3v(int* __restrict__ off, const int* __restrict__ bsums,
                         int* __restrict__ cur, const int* __restrict__ deg,
                         float* __restrict__ dinv, int n){
    int idx = blockIdx.x*blockDim.x + threadIdx.x;
    if (idx < n){
        int o = off[idx] + bsums[idx >> 10];
        off[idx] = o; cur[idx] = o;
        dinv[idx] = rsqrtf((float)(deg[idx] + 1));
    }
}
// ent-branch fixup: off += bsums; cur = off; lattr = ls / max(cnt,1)
__global__ void k_scan3e(int* __restrict__ off, const int* __restrict__ bsums,
                         int* __restrict__ cur, const int* __restrict__ cnt,
                         float* __restrict__ ls, int n){
    int idx = blockIdx.x*blockDim.x + threadIdx.x;
    if (idx < n){
        int o = off[idx] + bsums[idx >> 10];
        off[idx] = o; cur[idx] = o;
        ls[idx] = ls[idx] / fmaxf((float)cnt[idx], 1.f);
    }
}

// ---------------- elementwise / build kernels ----------------
__global__ void k_seti(int* p, int v, int n){
    int i = blockIdx.x*blockDim.x + threadIdx.x; if (i < n) p[i] = v;
}
__global__ void k_init_gat(int* __restrict__ cnt, float* __restrict__ ls, int n){
    int i = blockIdx.x*blockDim.x + threadIdx.x;
    if (i < n){ cnt[i] = 0; ls[i] = 0.f; }
}
__global__ void k_deg_acc(const int2* __restrict__ ed, int* deg, int E){
    int i = blockIdx.x*blockDim.x + threadIdx.x;
    if (i < E) atomicAdd(deg + ed[i].y, 1);
}
__global__ void k_scat_val(const int2* __restrict__ ed, int* cur, int* csrc, int E){
    int i = blockIdx.x*blockDim.x + threadIdx.x;
    if (i >= E) return;
    int2 sd = ed[i];
    int pos = atomicAdd(cur + sd.y, 1);
    csrc[pos] = sd.x;
}
__global__ void k_gcn_csr(const float* __restrict__ h, const float* __restrict__ dinv,
                          const float* __restrict__ b, float* __restrict__ out,
                          const int* __restrict__ off, const int* __restrict__ deg,
                          const int* __restrict__ csrc, int M)
{
    int g = blockIdx.x*blockDim.x + threadIdx.x;
    int lane = g & 31, d = g >> 5;
    if (d >= M) return;
    float did = dinv[d];
    float4 hv = ((const float4*)(h + (size_t)d*D))[lane];
    float4 acc = *(const float4*)(b + lane*4);
    acc = f4axpy(did*did, hv, acc);
    int e0 = off[d], n = deg[d];
    for (int e = e0; e < e0 + n; ++e){
        int s = csrc[e];
        float nrm = dinv[s]*did;
        float4 xv = ((const float4*)(h + (size_t)s*D))[lane];
        acc = f4axpy(nrm, xv, acc);
    }
    ((float4*)(out + (size_t)d*D))[lane] = acc;
}
__global__ void k_cnt(const int2* __restrict__ ed, const float* __restrict__ lab,
                      int* cnt, float* ls, int E){
    int i = blockIdx.x*blockDim.x + threadIdx.x;
    if (i < E){ int d = ed[i].y; atomicAdd(cnt + d, 1); atomicAdd(ls + d, lab[i]); }
}
__global__ void k_ce2(const float* __restrict__ We1, const float* __restrict__ ae1,
                      const float* __restrict__ We2, const float* __restrict__ ae2){
    int t = threadIdx.x;
    int lane = t & 31, w = t >> 5;
    const float* We = w ? We2 : We1;
    const float* ae = w ? ae2 : ae1;
    float s = 0.f;
    for (int i = lane; i < D; i += 32) s += We[i]*ae[i];
#pragma unroll
    for (int o = 16; o; o >>= 1) s += __shfl_xor_sync(0xffffffffu, s, o);
    if (lane == 0) g_ce2[w] = s;
}
__global__ void k_att_fused(const float* __restrict__ hcat,
    const float* __restrict__ as1, const float* __restrict__ ad1,
    const float* __restrict__ as2, const float* __restrict__ ad2,
    const float* __restrict__ lattr, int M)
{
    int g = blockIdx.x*blockDim.x + threadIdx.x;
    int lane = g & 31, row = g >> 5;
    if (row >= M) return;
    const float4* hp = (const float4*)(hcat + (size_t)row*256);
    float4 h1v = hp[lane];
    float4 h2v = hp[lane + 32];
    float4 s1 = *(const float4*)(as1 + lane*4);
    float4 d1 = *(const float4*)(ad1 + lane*4);
    float4 s2 = *(const float4*)(as2 + lane*4);
    float4 d2 = *(const float4*)(ad2 + lane*4);
    float x1 = h1v.x*s1.x + h1v.y*s1.y + h1v.z*s1.z + h1v.w*s1.w;
    float y1 = h1v.x*d1.x + h1v.y*d1.y + h1v.z*d1.z + h1v.w*d1.w;
    float x2 = h2v.x*s2.x + h2v.y*s2.y + h2v.z*s2.z + h2v.w*s2.w;
    float y2 = h2v.x*d2.x + h2v.y*d2.y + h2v.z*d2.z + h2v.w*d2.w;
#pragma unroll
    for (int o = 16; o; o >>= 1){
        x1 += __shfl_xor_sync(0xffffffffu, x1, o);
        y1 += __shfl_xor_sync(0xffffffffu, y1, o);
        x2 += __shfl_xor_sync(0xffffffffu, x2, o);
        y2 += __shfl_xor_sync(0xffffffffu, y2, o);
    }
    if (lane == 0){
        float la = lattr[row];
        g_als2[row] = make_float2(x1, x2);
        g_ald2[row] = make_float2(y1, y2);
        float e1 = __expf(lrelu(x1 + y1 + la*g_ce2[0]));
        float e2 = __expf(lrelu(x2 + y2 + la*g_ce2[1]));
        g_eself2[row] = make_float2(e1, e2);
    }
}
__global__ void k_alpha_scat(const int2* __restrict__ ed, const float* __restrict__ lab,
                             int* cur, int E){
    int i = blockIdx.x*blockDim.x + threadIdx.x;
    if (i >= E) return;
    int2 sd = ed[i];
    float2 als = g_als2[sd.x];
    float2 ald = g_ald2[sd.y];
    float la = lab[i];
    float e1 = __expf(lrelu(als.x + ald.x + la*g_ce2[0]));
    float e2 = __expf(lrelu(als.y + ald.y + la*g_ce2[1]));
    int pos = atomicAdd(cur + sd.y, 1);
    g_gsrc[pos] = sd.x;
    g_gexp[pos] = make_float2(e1, e2);
}
__global__ void k_gat_csr(const float* __restrict__ hcat, const float4* __restrict__ ent,
                          const float* __restrict__ b1, const float* __restrict__ b2,
                          const int* __restrict__ off, const int* __restrict__ cnt,
                          float* __restrict__ out, int M)
{
    int g = blockIdx.x*blockDim.x + threadIdx.x;
    int lane = g & 31, d = g >> 5;
    if (d >= M) return;
    float2 es = g_eself2[d];
    const float4* hp = (const float4*)(hcat + (size_t)d*256);
    float4 h1v = hp[lane], h2v = hp[lane + 32];
    float z1 = es.x, z2 = es.y;
    float4 a1 = make_float4(es.x*h1v.x, es.x*h1v.y, es.x*h1v.z, es.x*h1v.w);
    float4 a2 = make_float4(es.y*h2v.x, es.y*h2v.y, es.y*h2v.z, es.y*h2v.w);
    int e0 = off[d], n = cnt[d];
    for (int e = e0; e < e0 + n; ++e){
        int s = g_gsrc[e];
        float2 ee = g_gexp[e];
        const float4* sp = (const float4*)(hcat + (size_t)s*256);
        a1 = f4axpy(ee.x, sp[lane], a1);
        a2 = f4axpy(ee.y, sp[lane + 32], a2);
        z1 += ee.x; z2 += ee.y;
    }
    float i1 = 1.f/(z1 + 1e-16f), i2 = 1.f/(z2 + 1e-16f);
    float4 ev = ent[(size_t)d*32 + lane];
    float4 bv1 = *(const float4*)(b1 + lane*4);
    float4 bv2 = *(const float4*)(b2 + lane*4);
    float4 o;
    o.x = ev.x + bv1.x + bv2.x + i1*a1.x + i2*a2.x;
    o.y = ev.y + bv1.y + bv2.y + i1*a1.y + i2*a2.y;
    o.z = ev.z + bv1.z + bv2.z + i1*a1.z + i2*a2.z;
    o.w = ev.w + bv1.w + bv2.w + i1*a1.w + i2*a2.w;
    ((float4*)(out + (size_t)d*D))[lane] = o;
}

// ---------------- launcher ----------------
extern "C" void kernel_launch(void* const* d_in, const int* in_sizes, int n_in,
                              void* d_out, int out_size)
{
    const int*   triples  = (const int*)  d_in[0];
    const int2*  ent_ed   = (const int2*) d_in[1];
    const float* ent_lab  = (const float*)d_in[2];
    const int2*  val_ed   = (const int2*) d_in[3];
    const float* att      = (const float*)d_in[5];
    const float* valf     = (const float*)d_in[6];
    const float* entf     = (const float*)d_in[7];
    const float* Wp       = (const float*)d_in[8];
    const float* g1W      = (const float*)d_in[9];
    const float* g1b      = (const float*)d_in[10];
    const float* g2W      = (const float*)d_in[11];
    const float* g2b      = (const float*)d_in[12];
    const float* Wl1      = (const float*)d_in[13];
    const float* as1      = (const float*)d_in[14];
    const float* ad1      = (const float*)d_in[15];
    const float* We1      = (const float*)d_in[16];
    const float* ae1      = (const float*)d_in[17];
    const float* gb1      = (const float*)d_in[18];
    const float* Wl2      = (const float*)d_in[19];
    const float* as2      = (const float*)d_in[20];
    const float* ad2      = (const float*)d_in[21];
    const float* We2      = (const float*)d_in[22];
    const float* ae2      = (const float*)d_in[23];
    const float* gb2      = (const float*)d_in[24];

    const int T   = in_sizes[0] / 3;
    const int E1  = in_sizes[1] / 2;
    const int E2  = in_sizes[3] / 2;
    const int NE  = in_sizes[7] / D;
    const int N   = NE + T;
    float* out = (float*)d_out;

    float *nodesA, *nodesB, *hbuf, *dinv, *lattr, *zerov;
    int *deg, *cnt, *off, *cur, *bsums, *csrc, *offE, *curE, *bsumsE;
    cudaGetSymbolAddress((void**)&nodesA, g_nodesA);
    cudaGetSymbolAddress((void**)&nodesB, g_nodesB);
    cudaGetSymbolAddress((void**)&hbuf,   g_hbuf);
    cudaGetSymbolAddress((void**)&dinv,   g_dinv);
    cudaGetSymbolAddress((void**)&deg,    g_deg);
    cudaGetSymbolAddress((void**)&cnt,    g_cnt);
    cudaGetSymbolAddress((void**)&lattr,  g_lattr);
    cudaGetSymbolAddress((void**)&zerov,  g_zerovec);
    cudaGetSymbolAddress((void**)&off,    g_off);
    cudaGetSymbolAddress((void**)&cur,    g_cur);
    cudaGetSymbolAddress((void**)&bsums,  g_bsums);
    cudaGetSymbolAddress((void**)&csrc,   g_csrc);
    cudaGetSymbolAddress((void**)&offE,   g_offE);
    cudaGetSymbolAddress((void**)&curE,   g_curE);
    cudaGetSymbolAddress((void**)&bsumsE, g_bsumsE);

    cudaFuncSetAttribute(k_gemm_mma,   cudaFuncAttributeMaxDynamicSharedMemorySize, SMEM_MMA);
    cudaFuncSetAttribute(k_valenc_mma, cudaFuncAttributeMaxDynamicSharedMemorySize, SMEM_MMA);

    const int TB = 256;
    #define GRID1(n) (((n) + TB - 1) / TB)

    // fork side branches off the capture origin (legacy stream)
    cudaStream_t sB, sC;
    cudaStreamCreateWithFlags(&sB, cudaStreamNonBlocking);
    cudaStreamCreateWithFlags(&sC, cudaStreamNonBlocking);
    cudaEvent_t eF, eB, eC;
    cudaEventCreateWithFlags(&eF, cudaEventDisableTiming);
    cudaEventCreateWithFlags(&eB, cudaEventDisableTiming);
    cudaEventCreateWithFlags(&eC, cudaEventDisableTiming);
    cudaEventRecord(eF, 0);
    cudaStreamWaitEvent(sB, eF, 0);
    cudaStreamWaitEvent(sC, eF, 0);

    // ---- branch B: val-edge CSR + dinv ----
    k_seti   <<<GRID1(N), TB, 0, sB>>>(deg, 0, N);
    k_deg_acc<<<GRID1(E2), TB, 0, sB>>>(val_ed, deg, E2);
    {
        int nb = (N + SCAN_B - 1)/SCAN_B;
        k_scan1<<<nb, SCAN_B, 0, sB>>>(deg, off, bsums, N);
        k_scan2<<<1, SCAN_B, 0, sB>>>(bsums, nb);
        k_scan3v<<<GRID1(N), TB, 0, sB>>>(off, bsums, cur, deg, dinv, N);
    }
    k_scat_val<<<GRID1(E2), TB, 0, sB>>>(val_ed, cur, csrc, E2);
    cudaEventRecord(eB, sB);

    // ---- branch C: ent-edge CSR offsets + lattr + ce2 ----
    k_init_gat<<<GRID1(NE), TB, 0, sC>>>(cnt, lattr, NE);
    k_cnt     <<<GRID1(E1), TB, 0, sC>>>(ent_ed, ent_lab, cnt, lattr, E1);
    {
        int nb = (NE + SCAN_B - 1)/SCAN_B;
        k_scan1<<<nb, SCAN_B, 0, sC>>>(cnt, offE, bsumsE, NE);
        k_scan2<<<1, SCAN_B, 0, sC>>>(bsumsE, nb);
        k_scan3e<<<GRID1(NE), TB, 0, sC>>>(offE, bsumsE, curE, cnt, lattr, NE);
    }
    k_ce2<<<1, 64, 0, sC>>>(We1, ae1, We2, ae2);
    cudaEventRecord(eC, sC);

    // ---- main: value encoder + GCN1 GEMM (dual-source A: entf | valfeat) ----
    float* valfeat = nodesA + (size_t)NE*D;   // only the high region of nodesA is written
    k_valenc_mma<<<(T + 63)/64, TB, SMEM_MMA>>>(triples, att, valf, Wp, valfeat, T);
    k_gemm_mma<<<(N + 63)/64, TB, SMEM_MMA>>>(entf, valfeat, NE, g1W, hbuf,
                                              (const float*)0, D, N);

    // join B: need CSR + dinv for aggregation
    cudaStreamWaitEvent(0, eB, 0);
    k_gcn_csr<<<GRID1(N*32), TB>>>(hbuf, dinv, g1b, nodesB, off, deg, csrc, N);
    k_gcn_csr<<<GRID1(NE*32), TB>>>(nodesB, dinv, zerov, nodesA, off, deg, csrc, NE);
    k_gemm_mma<<<(NE + 63)/64, TB, SMEM_MMA>>>(nodesA, nodesA, NE, g2W, hbuf, g2b, D, NE);

    // ---- GAT GEMMs into interleaved hcat (row stride 256) ----
    float* hcat = nodesA;
    k_gemm_mma<<<(NE + 63)/64, TB, SMEM_MMA>>>(hbuf, hbuf, NE, Wl1, hcat,
                                               (const float*)0, 256, NE);
    k_gemm_mma<<<(NE + 63)/64, TB, SMEM_MMA>>>(hbuf, hbuf, NE, Wl2, hcat + 128,
                                               (const float*)0, 256, NE);

    // join C: lattr/ce2/CSR offsets for attention
    cudaStreamWaitEvent(0, eC, 0);
    k_att_fused <<<(NE + 7)/8, TB>>>(hcat, as1, ad1, as2, ad2, lattr, NE);
    k_alpha_scat<<<GRID1(E1), TB>>>(ent_ed, ent_lab, curE, E1);
    k_gat_csr   <<<GRID1(NE*32), TB>>>(hcat, (const float4*)entf, gb1, gb2,
                                       offE, cnt, out, NE);

    cudaEventDestroy(eF); cudaEventDestroy(eB); cudaEventDestroy(eC);
    cudaStreamDestroy(sB); cudaStreamDestroy(sC);
    #undef GRID1
}